// round 1
// baseline (speedup 1.0000x reference)
#include <cuda_runtime.h>
#include <cuda_bf16.h>
#include <cstdint>
#include <cstddef>

// Problem constants
#define BATCH 2
#define SEQ   4096
#define EMB   512
#define HEADS 8
#define DHEAD 64

// Scratch buffers (allocation-free rule: __device__ globals)
__device__ float g_q[BATCH * SEQ * EMB];
__device__ float g_k[BATCH * SEQ * EMB];
__device__ float g_v[BATCH * SEQ * EMB];
__device__ float g_o[BATCH * SEQ * EMB];

// ---------------------------------------------------------------------------
// GEMM: Y[M,N] = X[M,K] @ W[N,K]^T + bias[N]   (M=8192, N=K=512)
// 64x64 tile per CTA, 256 threads, 4x4 per thread, kt=32.
// ---------------------------------------------------------------------------
__global__ __launch_bounds__(256) void gemm_nt_kernel(
    const float* __restrict__ X, const float* __restrict__ W,
    const float* __restrict__ bias, float* __restrict__ Y) {
  const int Kd = EMB, Nd = EMB;
  __shared__ float sX[64 * 33];
  __shared__ float sW[64 * 33];

  const int m0 = blockIdx.x * 64;
  const int n0 = blockIdx.y * 64;
  const int t = threadIdx.x;
  const int tx = t & 15;
  const int ty = t >> 4;

  float acc[4][4];
#pragma unroll
  for (int i = 0; i < 4; i++)
#pragma unroll
    for (int j = 0; j < 4; j++) acc[i][j] = 0.f;

  for (int k0 = 0; k0 < Kd; k0 += 32) {
#pragma unroll
    for (int i = 0; i < 2; i++) {
      int idx = t + 256 * i;          // 0..511
      int r = idx >> 3;               // 0..63
      int c = (idx & 7) << 2;         // 0..28 step 4
      float4 xv = *reinterpret_cast<const float4*>(X + (size_t)(m0 + r) * Kd + k0 + c);
      float* dx = sX + r * 33 + c;
      dx[0] = xv.x; dx[1] = xv.y; dx[2] = xv.z; dx[3] = xv.w;
      float4 wv = *reinterpret_cast<const float4*>(W + (size_t)(n0 + r) * Kd + k0 + c);
      float* dw = sW + r * 33 + c;
      dw[0] = wv.x; dw[1] = wv.y; dw[2] = wv.z; dw[3] = wv.w;
    }
    __syncthreads();

#pragma unroll
    for (int k = 0; k < 32; k++) {
      float xf[4], wf[4];
#pragma unroll
      for (int i = 0; i < 4; i++) xf[i] = sX[(ty + 16 * i) * 33 + k];
#pragma unroll
      for (int j = 0; j < 4; j++) wf[j] = sW[(tx + 16 * j) * 33 + k];
#pragma unroll
      for (int i = 0; i < 4; i++)
#pragma unroll
        for (int j = 0; j < 4; j++) acc[i][j] = fmaf(xf[i], wf[j], acc[i][j]);
    }
    __syncthreads();
  }

#pragma unroll
  for (int i = 0; i < 4; i++) {
    float* yr = Y + (size_t)(m0 + ty + 16 * i) * Nd + n0;
#pragma unroll
    for (int j = 0; j < 4; j++) {
      int n = tx + 16 * j;
      yr[n] = acc[i][j] + bias[n0 + n];
    }
  }
}

// ---------------------------------------------------------------------------
// Flash attention per (head, batch): 64-query tile per CTA, stream 64-key
// tiles with online softmax. scores = (QK^T + bias, masked) / sqrt(D).
// ---------------------------------------------------------------------------
#define STR 65
#define ATTN_SMEM (4 * 64 * STR * (int)sizeof(float))

__global__ __launch_bounds__(256) void attn_kernel(
    const float* __restrict__ Qg, const float* __restrict__ Kg,
    const float* __restrict__ Vg, const float* __restrict__ bias,
    const int* __restrict__ mask, float* __restrict__ Og) {
  extern __shared__ float sm[];
  float* sQ = sm;                 // [64][STR]
  float* sK = sm + 64 * STR;
  float* sV = sm + 2 * 64 * STR;
  float* sP = sm + 3 * 64 * STR;

  const int q0 = blockIdx.x * 64;
  const int h = blockIdx.y >> 1;
  const int b = blockIdx.y & 1;

  const float* Qb = Qg + (size_t)b * SEQ * EMB + h * DHEAD;
  const float* Kb = Kg + (size_t)b * SEQ * EMB + h * DHEAD;
  const float* Vb = Vg + (size_t)b * SEQ * EMB + h * DHEAD;
  const float* Bb = bias + (size_t)h * SEQ * SEQ;

  const int t = threadIdx.x;
  const int tx = t & 15;
  const int ty = t >> 4;

  // Load Q tile (64 rows x 64 dims), coalesced float4
#pragma unroll
  for (int i = 0; i < 4; i++) {
    int idx = t + 256 * i;
    int r = idx >> 4;
    int c = (idx & 15) << 2;
    float4 v = *reinterpret_cast<const float4*>(Qb + (size_t)(q0 + r) * EMB + c);
    float* d = sQ + r * STR + c;
    d[0] = v.x; d[1] = v.y; d[2] = v.z; d[3] = v.w;
  }

  float m_i[4], l_i[4], acc[4][4];
#pragma unroll
  for (int i = 0; i < 4; i++) {
    m_i[i] = -1e30f;
    l_i[i] = 0.f;
#pragma unroll
    for (int j = 0; j < 4; j++) acc[i][j] = 0.f;
  }

  for (int k0 = 0; k0 < SEQ; k0 += 64) {
    __syncthreads();  // previous PV reads of sK/sV/sP done
#pragma unroll
    for (int i = 0; i < 4; i++) {
      int idx = t + 256 * i;
      int r = idx >> 4;
      int c = (idx & 15) << 2;
      float4 kv = *reinterpret_cast<const float4*>(Kb + (size_t)(k0 + r) * EMB + c);
      float* dk = sK + r * STR + c;
      dk[0] = kv.x; dk[1] = kv.y; dk[2] = kv.z; dk[3] = kv.w;
      float4 vv = *reinterpret_cast<const float4*>(Vb + (size_t)(k0 + r) * EMB + c);
      float* dv = sV + r * STR + c;
      dv[0] = vv.x; dv[1] = vv.y; dv[2] = vv.z; dv[3] = vv.w;
    }
    __syncthreads();

    // S = Q @ K^T  (thread: q rows {ty+16i}, k cols {tx+16j})
    float s[4][4];
#pragma unroll
    for (int i = 0; i < 4; i++)
#pragma unroll
      for (int j = 0; j < 4; j++) s[i][j] = 0.f;

#pragma unroll 4
    for (int d = 0; d < 64; d++) {
      float qf[4], kf[4];
#pragma unroll
      for (int i = 0; i < 4; i++) qf[i] = sQ[(ty + 16 * i) * STR + d];
#pragma unroll
      for (int j = 0; j < 4; j++) kf[j] = sK[(tx + 16 * j) * STR + d];
#pragma unroll
      for (int i = 0; i < 4; i++)
#pragma unroll
        for (int j = 0; j < 4; j++) s[i][j] = fmaf(qf[i], kf[j], s[i][j]);
    }

    // bias + mask + scale; per-row max
    float mloc[4];
#pragma unroll
    for (int i = 0; i < 4; i++) {
      int qg = q0 + ty + 16 * i;
      const float* brow = Bb + (size_t)qg * SEQ + k0;
      const int* mrow = mask + (size_t)qg * SEQ + k0;
      float mx = -1e30f;
#pragma unroll
      for (int j = 0; j < 4; j++) {
        int kc = tx + 16 * j;
        float sv = (s[i][j] + brow[kc]) * 0.125f;
        sv = mrow[kc] ? sv : -1e20f;
        s[i][j] = sv;
        mx = fmaxf(mx, sv);
      }
      mloc[i] = mx;
    }
    // reduce max over the 16 lanes of this row group
#pragma unroll
    for (int off = 8; off >= 1; off >>= 1) {
#pragma unroll
      for (int i = 0; i < 4; i++)
        mloc[i] = fmaxf(mloc[i], __shfl_xor_sync(0xffffffffu, mloc[i], off));
    }

#pragma unroll
    for (int i = 0; i < 4; i++) {
      float mnew = fmaxf(m_i[i], mloc[i]);
      float corr = __expf(m_i[i] - mnew);
      m_i[i] = mnew;
      float ls = 0.f;
#pragma unroll
      for (int j = 0; j < 4; j++) {
        float p = __expf(s[i][j] - mnew);
        s[i][j] = p;
        ls += p;
      }
#pragma unroll
      for (int off = 8; off >= 1; off >>= 1)
        ls += __shfl_xor_sync(0xffffffffu, ls, off);
      l_i[i] = l_i[i] * corr + ls;
#pragma unroll
      for (int j = 0; j < 4; j++) acc[i][j] *= corr;
    }

    // stash P
#pragma unroll
    for (int i = 0; i < 4; i++)
#pragma unroll
      for (int j = 0; j < 4; j++)
        sP[(ty + 16 * i) * STR + tx + 16 * j] = s[i][j];
    __syncthreads();

    // acc += P @ V  (thread: q rows {ty+16i}, d cols {tx+16j})
#pragma unroll 4
    for (int kk = 0; kk < 64; kk++) {
      float pf[4], vf[4];
#pragma unroll
      for (int i = 0; i < 4; i++) pf[i] = sP[(ty + 16 * i) * STR + kk];
#pragma unroll
      for (int j = 0; j < 4; j++) vf[j] = sV[kk * STR + tx + 16 * j];
#pragma unroll
      for (int i = 0; i < 4; i++)
#pragma unroll
        for (int j = 0; j < 4; j++) acc[i][j] = fmaf(pf[i], vf[j], acc[i][j]);
    }
  }

  // epilogue: write O in [B,S,E] layout (merge heads back)
#pragma unroll
  for (int i = 0; i < 4; i++) {
    int qg = q0 + ty + 16 * i;
    float inv = 1.0f / l_i[i];
    float* orow = Og + (size_t)(b * SEQ + qg) * EMB + h * DHEAD;
#pragma unroll
    for (int j = 0; j < 4; j++) orow[tx + 16 * j] = acc[i][j] * inv;
  }
}

// ---------------------------------------------------------------------------
extern "C" void kernel_launch(void* const* d_in, const int* in_sizes, int n_in,
                              void* d_out, int out_size) {
  const float* x    = (const float*)d_in[0];
  const float* bias = (const float*)d_in[1];
  const int*   mask = (const int*)d_in[2];
  const float* Wq   = (const float*)d_in[3];
  const float* bq   = (const float*)d_in[4];
  const float* Wk   = (const float*)d_in[5];
  const float* bk   = (const float*)d_in[6];
  const float* Wv   = (const float*)d_in[7];
  const float* bv   = (const float*)d_in[8];
  const float* Wo   = (const float*)d_in[9];
  const float* bo   = (const float*)d_in[10];
  float* out = (float*)d_out;

  float *pq, *pk, *pv, *po;
  cudaGetSymbolAddress((void**)&pq, g_q);
  cudaGetSymbolAddress((void**)&pk, g_k);
  cudaGetSymbolAddress((void**)&pv, g_v);
  cudaGetSymbolAddress((void**)&po, g_o);

  dim3 gg(BATCH * SEQ / 64, EMB / 64);  // (128, 8)
  gemm_nt_kernel<<<gg, 256>>>(x, Wq, bq, pq);
  gemm_nt_kernel<<<gg, 256>>>(x, Wk, bk, pk);
  gemm_nt_kernel<<<gg, 256>>>(x, Wv, bv, pv);

  cudaFuncSetAttribute(attn_kernel, cudaFuncAttributeMaxDynamicSharedMemorySize,
                       ATTN_SMEM);
  dim3 ga(SEQ / 64, HEADS * BATCH);  // (64, 16)
  attn_kernel<<<ga, 256, ATTN_SMEM>>>(pq, pk, pv, bias, mask, po);

  gemm_nt_kernel<<<gg, 256>>>(po, Wo, bo, out);
}

// round 2
// speedup vs baseline: 2.1239x; 2.1239x over previous
#include <cuda_runtime.h>
#include <cuda_bf16.h>
#include <cstdint>
#include <cstddef>

#define BATCH 2
#define SEQ   4096
#define EMB   512
#define HEADS 8
#define DHEAD 64

// Scratch (allocation-free rule: __device__ globals)
__device__ float g_q[BATCH * SEQ * EMB];
__device__ float g_k[BATCH * SEQ * EMB];
__device__ float g_v[BATCH * SEQ * EMB];
__device__ float g_o[BATCH * SEQ * EMB];

__device__ __forceinline__ uint32_t f2tf32(float f) {
  uint32_t u;
  asm("cvt.rna.tf32.f32 %0, %1;" : "=r"(u) : "f"(f));
  return u;
}

__device__ __forceinline__ void mma_tf32(float c[4], uint32_t a0, uint32_t a1,
                                         uint32_t a2, uint32_t a3, uint32_t b0,
                                         uint32_t b1) {
  asm volatile(
      "mma.sync.aligned.m16n8k8.row.col.f32.tf32.tf32.f32 "
      "{%0,%1,%2,%3},{%4,%5,%6,%7},{%8,%9},{%0,%1,%2,%3};"
      : "+f"(c[0]), "+f"(c[1]), "+f"(c[2]), "+f"(c[3])
      : "r"(a0), "r"(a1), "r"(a2), "r"(a3), "r"(b0), "r"(b1));
}

// ---------------------------------------------------------------------------
// GEMM: Y[M,N] = X[M,K] @ W[N,K]^T + bias[N]  via mma.sync tf32
// CTA: 128 rows x 64 cols, 8 warps (16 rows each), K-chunks of 64.
// ---------------------------------------------------------------------------
#define GX_STR 68
#define GW_STR 68
#define GEMM_SMEM ((128 * GX_STR + 64 * GW_STR) * (int)sizeof(float))

__global__ __launch_bounds__(256) void gemm_mma_kernel(
    const float* __restrict__ X, const float* __restrict__ W,
    const float* __restrict__ bias, float* __restrict__ Y) {
  extern __shared__ float sm[];
  float* sX = sm;                 // [128][GX_STR]
  float* sW = sm + 128 * GX_STR;  // [64][GW_STR]

  const int Kd = EMB, Nd = EMB;
  const int m0 = blockIdx.x * 128;
  const int n0 = blockIdx.y * 64;
  const int t = threadIdx.x;
  const int w = t >> 5;
  const int lane = t & 31;
  const int r4 = lane >> 2;  // 0..7
  const int c4 = lane & 3;   // 0..3

  float acc[8][4];
#pragma unroll
  for (int nt = 0; nt < 8; nt++)
#pragma unroll
    for (int j = 0; j < 4; j++) acc[nt][j] = 0.f;

  for (int kc = 0; kc < Kd; kc += 64) {
    __syncthreads();
    // load X tile 128x64 (8 float4 per thread)
#pragma unroll
    for (int i = 0; i < 8; i++) {
      int idx = t + 256 * i;
      int r = idx >> 4;
      int c = (idx & 15) << 2;
      float4 v = *reinterpret_cast<const float4*>(X + (size_t)(m0 + r) * Kd + kc + c);
      float* d = sX + r * GX_STR + c;
      d[0] = __uint_as_float(f2tf32(v.x));
      d[1] = __uint_as_float(f2tf32(v.y));
      d[2] = __uint_as_float(f2tf32(v.z));
      d[3] = __uint_as_float(f2tf32(v.w));
    }
    // load W tile 64x64 (4 float4 per thread)
#pragma unroll
    for (int i = 0; i < 4; i++) {
      int idx = t + 256 * i;
      int r = idx >> 4;
      int c = (idx & 15) << 2;
      float4 v = *reinterpret_cast<const float4*>(W + (size_t)(n0 + r) * Kd + kc + c);
      float* d = sW + r * GW_STR + c;
      d[0] = __uint_as_float(f2tf32(v.x));
      d[1] = __uint_as_float(f2tf32(v.y));
      d[2] = __uint_as_float(f2tf32(v.z));
      d[3] = __uint_as_float(f2tf32(v.w));
    }
    __syncthreads();

#pragma unroll
    for (int ks = 0; ks < 8; ks++) {
      const float* ax = sX + (16 * w + r4) * GX_STR + 8 * ks + c4;
      uint32_t a0 = __float_as_uint(ax[0]);
      uint32_t a1 = __float_as_uint(ax[8 * GX_STR]);
      uint32_t a2 = __float_as_uint(ax[4]);
      uint32_t a3 = __float_as_uint(ax[8 * GX_STR + 4]);
#pragma unroll
      for (int nt = 0; nt < 8; nt++) {
        const float* bx = sW + (8 * nt + r4) * GW_STR + 8 * ks + c4;
        uint32_t b0 = __float_as_uint(bx[0]);
        uint32_t b1 = __float_as_uint(bx[4]);
        mma_tf32(acc[nt], a0, a1, a2, a3, b0, b1);
      }
    }
  }

  // epilogue
  const int row0 = m0 + 16 * w + r4;
#pragma unroll
  for (int nt = 0; nt < 8; nt++) {
    int col = n0 + 8 * nt + 2 * c4;
    float b0 = bias[col], b1 = bias[col + 1];
    float2 v0 = make_float2(acc[nt][0] + b0, acc[nt][1] + b1);
    float2 v1 = make_float2(acc[nt][2] + b0, acc[nt][3] + b1);
    *reinterpret_cast<float2*>(Y + (size_t)row0 * Nd + col) = v0;
    *reinterpret_cast<float2*>(Y + (size_t)(row0 + 8) * Nd + col) = v1;
  }
}

// ---------------------------------------------------------------------------
// Flash attention via mma.sync tf32.
// CTA: 128 queries, 8 warps x 16 rows. Stream 64-key tiles.
// Key-permutation trick: S C-fragments feed PV A-fragments in registers.
// ---------------------------------------------------------------------------
#define K_STR 68
#define V_STR 72
#define SQA_FLOATS (8 * 8 * 32 * 4)  // 8192
#define ATTN_SMEM ((SQA_FLOATS + 64 * K_STR + 64 * V_STR) * (int)sizeof(float))

__global__ __launch_bounds__(256) void attn_mma_kernel(
    const float* __restrict__ Qg, const float* __restrict__ Kg,
    const float* __restrict__ Vg, const float* __restrict__ bias,
    const int* __restrict__ mask, float* __restrict__ Og) {
  extern __shared__ float sm[];
  float* sQa = sm;                    // fragment-native Q [w][ks][lane][4]
  float* sK = sm + SQA_FLOATS;        // [64][K_STR]
  float* sV = sK + 64 * K_STR;        // [64][V_STR]
  float* sQflat = sm + SQA_FLOATS;    // staging (overlaps sK/sV)

  const int q0 = blockIdx.x * 128;
  const int h = blockIdx.y >> 1;
  const int b = blockIdx.y & 1;

  const float* Qb = Qg + (size_t)b * SEQ * EMB + h * DHEAD;
  const float* Kb = Kg + (size_t)b * SEQ * EMB + h * DHEAD;
  const float* Vb = Vg + (size_t)b * SEQ * EMB + h * DHEAD;
  const float* Bb = bias + (size_t)h * SEQ * SEQ;

  const int t = threadIdx.x;
  const int w = t >> 5;
  const int lane = t & 31;
  const int r4 = lane >> 2;
  const int c4 = lane & 3;
  const int permr = ((r4 & 1) << 2) | (r4 >> 1);  // [0,4,1,5,2,6,3,7]

  // --- stage Q: coalesced load (tf32) into flat buffer ---
#pragma unroll
  for (int i = 0; i < 8; i++) {
    int idx = t + 256 * i;
    int r = idx >> 4;
    int c = (idx & 15) << 2;
    float4 v = *reinterpret_cast<const float4*>(Qb + (size_t)(q0 + r) * EMB + c);
    float* d = sQflat + r * 64 + c;
    d[0] = __uint_as_float(f2tf32(v.x));
    d[1] = __uint_as_float(f2tf32(v.y));
    d[2] = __uint_as_float(f2tf32(v.z));
    d[3] = __uint_as_float(f2tf32(v.w));
  }
  __syncthreads();
  // rearrange into fragment-native layout
  {
    float frag[8][4];
#pragma unroll
    for (int s0 = 0; s0 < 8; s0++) {
      // slot s = t + 256*s0 -> w' = s0, ks = w, l = lane
      int row = 16 * s0 + r4;
      int col = 8 * w + c4;
      frag[s0][0] = sQflat[row * 64 + col];
      frag[s0][1] = sQflat[(row + 8) * 64 + col];
      frag[s0][2] = sQflat[row * 64 + col + 4];
      frag[s0][3] = sQflat[(row + 8) * 64 + col + 4];
    }
    __syncthreads();
#pragma unroll
    for (int s0 = 0; s0 < 8; s0++) {
      int s = t + 256 * s0;
      *reinterpret_cast<float4*>(sQa + s * 4) =
          make_float4(frag[s0][0], frag[s0][1], frag[s0][2], frag[s0][3]);
    }
  }

  const int qr0 = q0 + 16 * w + r4;
  const int qr1 = qr0 + 8;

  float m0 = -1e30f, m1 = -1e30f, l0 = 0.f, l1 = 0.f;
  float acc[8][4];
#pragma unroll
  for (int nt = 0; nt < 8; nt++)
#pragma unroll
    for (int j = 0; j < 4; j++) acc[nt][j] = 0.f;

  for (int k0 = 0; k0 < SEQ; k0 += 64) {
    __syncthreads();  // prior-iter smem reads done
    // load K,V tiles (64x64 each, 4 float4 per thread each)
#pragma unroll
    for (int i = 0; i < 4; i++) {
      int idx = t + 256 * i;
      int r = idx >> 4;
      int c = (idx & 15) << 2;
      float4 kv = *reinterpret_cast<const float4*>(Kb + (size_t)(k0 + r) * EMB + c);
      float* dk = sK + r * K_STR + c;
      dk[0] = __uint_as_float(f2tf32(kv.x));
      dk[1] = __uint_as_float(f2tf32(kv.y));
      dk[2] = __uint_as_float(f2tf32(kv.z));
      dk[3] = __uint_as_float(f2tf32(kv.w));
      float4 vv = *reinterpret_cast<const float4*>(Vb + (size_t)(k0 + r) * EMB + c);
      float* dv = sV + r * V_STR + c;
      dv[0] = __uint_as_float(f2tf32(vv.x));
      dv[1] = __uint_as_float(f2tf32(vv.y));
      dv[2] = __uint_as_float(f2tf32(vv.z));
      dv[3] = __uint_as_float(f2tf32(vv.w));
    }
    __syncthreads();

    // ---- S = Q @ K^T (logical cols permuted) ----
    float S[8][4];
#pragma unroll
    for (int nt = 0; nt < 8; nt++)
#pragma unroll
      for (int j = 0; j < 4; j++) S[nt][j] = 0.f;

#pragma unroll
    for (int ks = 0; ks < 8; ks++) {
      float4 av = *reinterpret_cast<const float4*>(sQa + ((w * 8 + ks) * 32 + lane) * 4);
      uint32_t a0 = __float_as_uint(av.x);
      uint32_t a1 = __float_as_uint(av.y);
      uint32_t a2 = __float_as_uint(av.z);
      uint32_t a3 = __float_as_uint(av.w);
      const float* kb = sK + permr * K_STR + 8 * ks + c4;
#pragma unroll
      for (int nt = 0; nt < 8; nt++) {
        uint32_t b0 = __float_as_uint(kb[8 * nt * K_STR]);
        uint32_t b1 = __float_as_uint(kb[8 * nt * K_STR + 4]);
        mma_tf32(S[nt], a0, a1, a2, a3, b0, b1);
      }
    }

    // ---- bias + mask + scale; row max ----
    // thread's physical key cols: c0 -> 8nt+c4, c1 -> 8nt+c4+4 (perm trick)
    float mx0 = -1e30f, mx1 = -1e30f;
    const float* br0 = Bb + (size_t)qr0 * SEQ + k0;
    const float* br1 = Bb + (size_t)qr1 * SEQ + k0;
    const int* mr0 = mask + (size_t)qr0 * SEQ + k0;
    const int* mr1 = mask + (size_t)qr1 * SEQ + k0;
#pragma unroll
    for (int nt = 0; nt < 8; nt++) {
      int kcol = 8 * nt + c4;
      float s0a = mr0[kcol] ? (S[nt][0] + br0[kcol]) * 0.125f : -1e20f;
      float s0b = mr0[kcol + 4] ? (S[nt][1] + br0[kcol + 4]) * 0.125f : -1e20f;
      float s1a = mr1[kcol] ? (S[nt][2] + br1[kcol]) * 0.125f : -1e20f;
      float s1b = mr1[kcol + 4] ? (S[nt][3] + br1[kcol + 4]) * 0.125f : -1e20f;
      S[nt][0] = s0a; S[nt][1] = s0b; S[nt][2] = s1a; S[nt][3] = s1b;
      mx0 = fmaxf(mx0, fmaxf(s0a, s0b));
      mx1 = fmaxf(mx1, fmaxf(s1a, s1b));
    }
    mx0 = fmaxf(mx0, __shfl_xor_sync(0xffffffffu, mx0, 1));
    mx0 = fmaxf(mx0, __shfl_xor_sync(0xffffffffu, mx0, 2));
    mx1 = fmaxf(mx1, __shfl_xor_sync(0xffffffffu, mx1, 1));
    mx1 = fmaxf(mx1, __shfl_xor_sync(0xffffffffu, mx1, 2));

    float mn0 = fmaxf(m0, mx0);
    float mn1 = fmaxf(m1, mx1);
    float corr0 = __expf(m0 - mn0);
    float corr1 = __expf(m1 - mn1);
    m0 = mn0; m1 = mn1;

    float sum0 = 0.f, sum1 = 0.f;
#pragma unroll
    for (int nt = 0; nt < 8; nt++) {
      float p0 = __expf(S[nt][0] - mn0);
      float p1 = __expf(S[nt][1] - mn0);
      float p2 = __expf(S[nt][2] - mn1);
      float p3 = __expf(S[nt][3] - mn1);
      S[nt][0] = p0; S[nt][1] = p1; S[nt][2] = p2; S[nt][3] = p3;
      sum0 += p0 + p1;
      sum1 += p2 + p3;
    }
    sum0 += __shfl_xor_sync(0xffffffffu, sum0, 1);
    sum0 += __shfl_xor_sync(0xffffffffu, sum0, 2);
    sum1 += __shfl_xor_sync(0xffffffffu, sum1, 1);
    sum1 += __shfl_xor_sync(0xffffffffu, sum1, 2);
    l0 = l0 * corr0 + sum0;
    l1 = l1 * corr1 + sum1;

#pragma unroll
    for (int nt = 0; nt < 8; nt++) {
      acc[nt][0] *= corr0; acc[nt][1] *= corr0;
      acc[nt][2] *= corr1; acc[nt][3] *= corr1;
    }

    // ---- PV: A-fragments directly from S regs (perm trick) ----
    uint32_t P[8][4];
#pragma unroll
    for (int nt = 0; nt < 8; nt++) {
      P[nt][0] = f2tf32(S[nt][0]);
      P[nt][1] = f2tf32(S[nt][1]);
      P[nt][2] = f2tf32(S[nt][2]);
      P[nt][3] = f2tf32(S[nt][3]);
    }
#pragma unroll
    for (int t8 = 0; t8 < 8; t8++) {
      uint32_t a0 = P[t8][0];  // (row, k=c4)
      uint32_t a1 = P[t8][2];  // (row+8, k=c4)
      uint32_t a2 = P[t8][1];  // (row, k=c4+4)
      uint32_t a3 = P[t8][3];  // (row+8, k=c4+4)
      const float* vb = sV + (8 * t8 + c4) * V_STR + r4;
#pragma unroll
      for (int nt = 0; nt < 8; nt++) {
        uint32_t b0 = __float_as_uint(vb[8 * nt]);
        uint32_t b1 = __float_as_uint(vb[4 * V_STR + 8 * nt]);
        mma_tf32(acc[nt], a0, a1, a2, a3, b0, b1);
      }
    }
  }

  // ---- epilogue ----
  float inv0 = 1.0f / l0;
  float inv1 = 1.0f / l1;
  float* o0 = Og + (size_t)(b * SEQ + qr0) * EMB + h * DHEAD;
  float* o1 = Og + (size_t)(b * SEQ + qr1) * EMB + h * DHEAD;
#pragma unroll
  for (int nt = 0; nt < 8; nt++) {
    int col = 8 * nt + 2 * c4;
    *reinterpret_cast<float2*>(o0 + col) =
        make_float2(acc[nt][0] * inv0, acc[nt][1] * inv0);
    *reinterpret_cast<float2*>(o1 + col) =
        make_float2(acc[nt][2] * inv1, acc[nt][3] * inv1);
  }
}

// ---------------------------------------------------------------------------
extern "C" void kernel_launch(void* const* d_in, const int* in_sizes, int n_in,
                              void* d_out, int out_size) {
  const float* x    = (const float*)d_in[0];
  const float* bias = (const float*)d_in[1];
  const int*   mask = (const int*)d_in[2];
  const float* Wq   = (const float*)d_in[3];
  const float* bq   = (const float*)d_in[4];
  const float* Wk   = (const float*)d_in[5];
  const float* bk   = (const float*)d_in[6];
  const float* Wv   = (const float*)d_in[7];
  const float* bv   = (const float*)d_in[8];
  const float* Wo   = (const float*)d_in[9];
  const float* bo   = (const float*)d_in[10];
  float* out = (float*)d_out;

  float *pq, *pk, *pv, *po;
  cudaGetSymbolAddress((void**)&pq, g_q);
  cudaGetSymbolAddress((void**)&pk, g_k);
  cudaGetSymbolAddress((void**)&pv, g_v);
  cudaGetSymbolAddress((void**)&po, g_o);

  cudaFuncSetAttribute(gemm_mma_kernel,
                       cudaFuncAttributeMaxDynamicSharedMemorySize, GEMM_SMEM);
  cudaFuncSetAttribute(attn_mma_kernel,
                       cudaFuncAttributeMaxDynamicSharedMemorySize, ATTN_SMEM);

  dim3 gg(BATCH * SEQ / 128, EMB / 64);  // (64, 8)
  gemm_mma_kernel<<<gg, 256, GEMM_SMEM>>>(x, Wq, bq, pq);
  gemm_mma_kernel<<<gg, 256, GEMM_SMEM>>>(x, Wk, bk, pk);
  gemm_mma_kernel<<<gg, 256, GEMM_SMEM>>>(x, Wv, bv, pv);

  dim3 ga(SEQ / 128, HEADS * BATCH);  // (32, 16)
  attn_mma_kernel<<<ga, 256, ATTN_SMEM>>>(pq, pk, pv, bias, mask, po);

  gemm_mma_kernel<<<gg, 256, GEMM_SMEM>>>(po, Wo, bo, out);
}

// round 3
// speedup vs baseline: 2.6197x; 1.2334x over previous
#include <cuda_runtime.h>
#include <cuda_bf16.h>
#include <cstdint>
#include <cstddef>

#define BATCH 2
#define SEQ   4096
#define EMB   512
#define HEADS 8
#define DHEAD 64

// Scratch (allocation-free rule: __device__ globals)
__device__ float g_q[BATCH * SEQ * EMB];
__device__ float g_k[BATCH * SEQ * EMB];
__device__ float g_v[BATCH * SEQ * EMB];
__device__ float g_o[BATCH * SEQ * EMB];

__device__ __forceinline__ uint32_t f2tf32(float f) {
  uint32_t u;
  asm("cvt.rna.tf32.f32 %0, %1;" : "=r"(u) : "f"(f));
  return u;
}

__device__ __forceinline__ void mma_tf32(float c[4], uint32_t a0, uint32_t a1,
                                         uint32_t a2, uint32_t a3, uint32_t b0,
                                         uint32_t b1) {
  asm volatile(
      "mma.sync.aligned.m16n8k8.row.col.f32.tf32.tf32.f32 "
      "{%0,%1,%2,%3},{%4,%5,%6,%7},{%8,%9},{%0,%1,%2,%3};"
      : "+f"(c[0]), "+f"(c[1]), "+f"(c[2]), "+f"(c[3])
      : "r"(a0), "r"(a1), "r"(a2), "r"(a3), "r"(b0), "r"(b1));
}

__device__ __forceinline__ void cp16(uint32_t saddr, const void* gaddr) {
  asm volatile("cp.async.cg.shared.global [%0], [%1], 16;" ::"r"(saddr),
               "l"(gaddr));
}

// ---------------------------------------------------------------------------
// GEMM: Y[M,N] = X[M,K] @ W[N,K]^T + bias[N]  via mma.sync tf32 (unchanged R2)
// ---------------------------------------------------------------------------
#define GX_STR 68
#define GW_STR 68
#define GEMM_SMEM ((128 * GX_STR + 64 * GW_STR) * (int)sizeof(float))

__global__ __launch_bounds__(256) void gemm_mma_kernel(
    const float* __restrict__ X, const float* __restrict__ W,
    const float* __restrict__ bias, float* __restrict__ Y) {
  extern __shared__ float sm[];
  float* sX = sm;
  float* sW = sm + 128 * GX_STR;

  const int Kd = EMB, Nd = EMB;
  const int m0 = blockIdx.x * 128;
  const int n0 = blockIdx.y * 64;
  const int t = threadIdx.x;
  const int w = t >> 5;
  const int lane = t & 31;
  const int r4 = lane >> 2;
  const int c4 = lane & 3;

  float acc[8][4];
#pragma unroll
  for (int nt = 0; nt < 8; nt++)
#pragma unroll
    for (int j = 0; j < 4; j++) acc[nt][j] = 0.f;

  for (int kc = 0; kc < Kd; kc += 64) {
    __syncthreads();
#pragma unroll
    for (int i = 0; i < 8; i++) {
      int idx = t + 256 * i;
      int r = idx >> 4;
      int c = (idx & 15) << 2;
      float4 v = *reinterpret_cast<const float4*>(X + (size_t)(m0 + r) * Kd + kc + c);
      float* d = sX + r * GX_STR + c;
      d[0] = __uint_as_float(f2tf32(v.x));
      d[1] = __uint_as_float(f2tf32(v.y));
      d[2] = __uint_as_float(f2tf32(v.z));
      d[3] = __uint_as_float(f2tf32(v.w));
    }
#pragma unroll
    for (int i = 0; i < 4; i++) {
      int idx = t + 256 * i;
      int r = idx >> 4;
      int c = (idx & 15) << 2;
      float4 v = *reinterpret_cast<const float4*>(W + (size_t)(n0 + r) * Kd + kc + c);
      float* d = sW + r * GW_STR + c;
      d[0] = __uint_as_float(f2tf32(v.x));
      d[1] = __uint_as_float(f2tf32(v.y));
      d[2] = __uint_as_float(f2tf32(v.z));
      d[3] = __uint_as_float(f2tf32(v.w));
    }
    __syncthreads();

#pragma unroll
    for (int ks = 0; ks < 8; ks++) {
      const float* ax = sX + (16 * w + r4) * GX_STR + 8 * ks + c4;
      uint32_t a0 = __float_as_uint(ax[0]);
      uint32_t a1 = __float_as_uint(ax[8 * GX_STR]);
      uint32_t a2 = __float_as_uint(ax[4]);
      uint32_t a3 = __float_as_uint(ax[8 * GX_STR + 4]);
#pragma unroll
      for (int nt = 0; nt < 8; nt++) {
        const float* bx = sW + (8 * nt + r4) * GW_STR + 8 * ks + c4;
        uint32_t b0 = __float_as_uint(bx[0]);
        uint32_t b1 = __float_as_uint(bx[4]);
        mma_tf32(acc[nt], a0, a1, a2, a3, b0, b1);
      }
    }
  }

  const int row0 = m0 + 16 * w + r4;
#pragma unroll
  for (int nt = 0; nt < 8; nt++) {
    int col = n0 + 8 * nt + 2 * c4;
    float b0 = bias[col], b1 = bias[col + 1];
    *reinterpret_cast<float2*>(Y + (size_t)row0 * Nd + col) =
        make_float2(acc[nt][0] + b0, acc[nt][1] + b1);
    *reinterpret_cast<float2*>(Y + (size_t)(row0 + 8) * Nd + col) =
        make_float2(acc[nt][2] + b0, acc[nt][3] + b1);
  }
}

// ---------------------------------------------------------------------------
// Flash attention v3: Q-frags in regs, cp.async double-buffered K/V (raw fp32),
// bias+mask fused via coalesced LDG -> per-warp smem bounce. Perm trick for PV.
// ---------------------------------------------------------------------------
#define K_STR 68
#define V_STR 72
#define B_STR 68
#define SK_FLOATS (2 * 64 * K_STR)  // 8704
#define SV_FLOATS (2 * 64 * V_STR)  // 9216
#define SB_FLOATS (8 * 16 * B_STR)  // 8704
#define ATTN_SMEM ((SK_FLOATS + SV_FLOATS + SB_FLOATS) * (int)sizeof(float))

__global__ __launch_bounds__(256, 2) void attn_mma_kernel(
    const float* __restrict__ Qg, const float* __restrict__ Kg,
    const float* __restrict__ Vg, const float* __restrict__ bias,
    const int* __restrict__ mask, float* __restrict__ Og) {
  extern __shared__ float sm[];
  float* sK0 = sm;                      // [2][64*K_STR] raw fp32
  float* sV0 = sm + SK_FLOATS;          // [2][64*V_STR] raw fp32
  float* sB = sm + SK_FLOATS + SV_FLOATS;  // [8][16*B_STR] fused bias

  const int q0 = blockIdx.x * 128;
  const int h = blockIdx.y >> 1;
  const int b = blockIdx.y & 1;

  const float* Qb = Qg + (size_t)b * SEQ * EMB + h * DHEAD;
  const float* Kb = Kg + (size_t)b * SEQ * EMB + h * DHEAD;
  const float* Vb = Vg + (size_t)b * SEQ * EMB + h * DHEAD;
  const float* Bb = bias + (size_t)h * SEQ * SEQ;

  const int t = threadIdx.x;
  const int w = t >> 5;
  const int lane = t & 31;
  const int r4 = lane >> 2;
  const int c4 = lane & 3;
  const int permr = ((r4 & 1) << 2) | (r4 >> 1);  // [0,4,1,5,2,6,3,7]

  // ---- stage Q (raw) into sK region, then load fragments into registers ----
#pragma unroll
  for (int i = 0; i < 8; i++) {
    int idx = t + 256 * i;
    int r = idx >> 4;
    int c = (idx & 15) << 2;
    float4 v = *reinterpret_cast<const float4*>(Qb + (size_t)(q0 + r) * EMB + c);
    float* d = sm + r * 68 + c;
    d[0] = v.x; d[1] = v.y; d[2] = v.z; d[3] = v.w;
  }
  __syncthreads();
  uint32_t qa[8][4];
#pragma unroll
  for (int ks = 0; ks < 8; ks++) {
    const float* ax = sm + (16 * w + r4) * 68 + 8 * ks + c4;
    qa[ks][0] = f2tf32(ax[0]);
    qa[ks][1] = f2tf32(ax[8 * 68]);
    qa[ks][2] = f2tf32(ax[4]);
    qa[ks][3] = f2tf32(ax[8 * 68 + 4]);
  }
  __syncthreads();

  const int qr0 = q0 + 16 * w + r4;
  const int qr1 = qr0 + 8;
  float* sBw = sB + w * 16 * B_STR;

  float m0 = -1e30f, m1 = -1e30f, l0 = 0.f, l1 = 0.f;
  float acc[8][4];
#pragma unroll
  for (int nt = 0; nt < 8; nt++)
#pragma unroll
    for (int j = 0; j < 4; j++) acc[nt][j] = 0.f;

  const uint32_t suK = (uint32_t)__cvta_generic_to_shared(sK0);
  const uint32_t suV = (uint32_t)__cvta_generic_to_shared(sV0);

  // prologue: prefetch tile 0 into buffer 0
  {
#pragma unroll
    for (int i = 0; i < 4; i++) {
      int idx = t + 256 * i;
      int r = idx >> 4;
      int c = (idx & 15) << 2;
      cp16(suK + (r * K_STR + c) * 4, Kb + (size_t)r * EMB + c);
      cp16(suV + (r * V_STR + c) * 4, Vb + (size_t)r * EMB + c);
    }
    asm volatile("cp.async.commit_group;" ::: "memory");
  }

  for (int kt = 0; kt < 64; kt++) {
    const int cur = kt & 1;
    const float* sKc = sK0 + cur * 64 * K_STR;
    const float* sVc = sV0 + cur * 64 * V_STR;

    __syncthreads();  // prior iteration's reads of buf[cur^1] and sB complete

    if (kt + 1 < 64) {
      const int nxt = cur ^ 1;
      const float* Ksrc = Kb + (size_t)(kt + 1) * 64 * EMB;
      const float* Vsrc = Vb + (size_t)(kt + 1) * 64 * EMB;
      const uint32_t dK = suK + nxt * 64 * K_STR * 4;
      const uint32_t dV = suV + nxt * 64 * V_STR * 4;
#pragma unroll
      for (int i = 0; i < 4; i++) {
        int idx = t + 256 * i;
        int r = idx >> 4;
        int c = (idx & 15) << 2;
        cp16(dK + (r * K_STR + c) * 4, Ksrc + (size_t)r * EMB + c);
        cp16(dV + (r * V_STR + c) * 4, Vsrc + (size_t)r * EMB + c);
      }
    }
    asm volatile("cp.async.commit_group;" ::: "memory");

    // ---- fused bias+mask: coalesced LDG -> per-warp smem bounce ----
    {
      const int k0 = kt * 64;
      const int hl = lane >> 4;        // 0/1
      const int cl = (lane & 15) << 2; // 0..60
#pragma unroll
      for (int i = 0; i < 8; i++) {
        int rl = 2 * i + hl;
        size_t off = (size_t)(q0 + 16 * w + rl) * SEQ + k0 + cl;
        float4 bv = *reinterpret_cast<const float4*>(Bb + off);
        int4 mv = *reinterpret_cast<const int4*>(mask + off);
        float4 f;
        f.x = mv.x ? bv.x : -1e20f;
        f.y = mv.y ? bv.y : -1e20f;
        f.z = mv.z ? bv.z : -1e20f;
        f.w = mv.w ? bv.w : -1e20f;
        *reinterpret_cast<float4*>(sBw + rl * B_STR + cl) = f;
      }
    }

    asm volatile("cp.async.wait_group 1;" ::: "memory");
    __syncthreads();  // K/V tile ready + sB visible

    // ---- S = Q @ K^T (permuted cols) ----
    float S[8][4];
#pragma unroll
    for (int nt = 0; nt < 8; nt++)
#pragma unroll
      for (int j = 0; j < 4; j++) S[nt][j] = 0.f;

#pragma unroll
    for (int ks = 0; ks < 8; ks++) {
      const float* kb = sKc + permr * K_STR + 8 * ks + c4;
      uint32_t a0 = qa[ks][0], a1 = qa[ks][1], a2 = qa[ks][2], a3 = qa[ks][3];
#pragma unroll
      for (int nt = 0; nt < 8; nt++) {
        uint32_t b0 = f2tf32(kb[8 * nt * K_STR]);
        uint32_t b1 = f2tf32(kb[8 * nt * K_STR + 4]);
        mma_tf32(S[nt], a0, a1, a2, a3, b0, b1);
      }
    }

    // ---- apply fused bias (from smem bounce), scale, row max ----
    float mx0 = -1e30f, mx1 = -1e30f;
#pragma unroll
    for (int nt = 0; nt < 8; nt++) {
      int cc = 8 * nt + c4;
      float f0 = sBw[r4 * B_STR + cc];
      float f1 = sBw[r4 * B_STR + cc + 4];
      float f2 = sBw[(r4 + 8) * B_STR + cc];
      float f3 = sBw[(r4 + 8) * B_STR + cc + 4];
      float s0 = (S[nt][0] + f0) * 0.125f;
      float s1 = (S[nt][1] + f1) * 0.125f;
      float s2 = (S[nt][2] + f2) * 0.125f;
      float s3 = (S[nt][3] + f3) * 0.125f;
      S[nt][0] = s0; S[nt][1] = s1; S[nt][2] = s2; S[nt][3] = s3;
      mx0 = fmaxf(mx0, fmaxf(s0, s1));
      mx1 = fmaxf(mx1, fmaxf(s2, s3));
    }
    mx0 = fmaxf(mx0, __shfl_xor_sync(0xffffffffu, mx0, 1));
    mx0 = fmaxf(mx0, __shfl_xor_sync(0xffffffffu, mx0, 2));
    mx1 = fmaxf(mx1, __shfl_xor_sync(0xffffffffu, mx1, 1));
    mx1 = fmaxf(mx1, __shfl_xor_sync(0xffffffffu, mx1, 2));

    float mn0 = fmaxf(m0, mx0);
    float mn1 = fmaxf(m1, mx1);
    float corr0 = __expf(m0 - mn0);
    float corr1 = __expf(m1 - mn1);
    m0 = mn0; m1 = mn1;

    float sum0 = 0.f, sum1 = 0.f;
#pragma unroll
    for (int nt = 0; nt < 8; nt++) {
      float p0 = __expf(S[nt][0] - mn0);
      float p1 = __expf(S[nt][1] - mn0);
      float p2 = __expf(S[nt][2] - mn1);
      float p3 = __expf(S[nt][3] - mn1);
      S[nt][0] = p0; S[nt][1] = p1; S[nt][2] = p2; S[nt][3] = p3;
      sum0 += p0 + p1;
      sum1 += p2 + p3;
    }
    sum0 += __shfl_xor_sync(0xffffffffu, sum0, 1);
    sum0 += __shfl_xor_sync(0xffffffffu, sum0, 2);
    sum1 += __shfl_xor_sync(0xffffffffu, sum1, 1);
    sum1 += __shfl_xor_sync(0xffffffffu, sum1, 2);
    l0 = l0 * corr0 + sum0;
    l1 = l1 * corr1 + sum1;

#pragma unroll
    for (int nt = 0; nt < 8; nt++) {
      acc[nt][0] *= corr0; acc[nt][1] *= corr0;
      acc[nt][2] *= corr1; acc[nt][3] *= corr1;
    }

    // ---- PV: A-fragments from S regs (perm trick) ----
#pragma unroll
    for (int t8 = 0; t8 < 8; t8++) {
      uint32_t a0 = f2tf32(S[t8][0]);
      uint32_t a1 = f2tf32(S[t8][2]);
      uint32_t a2 = f2tf32(S[t8][1]);
      uint32_t a3 = f2tf32(S[t8][3]);
      const float* vb = sVc + (8 * t8 + c4) * V_STR + r4;
#pragma unroll
      for (int nt = 0; nt < 8; nt++) {
        uint32_t b0 = f2tf32(vb[8 * nt]);
        uint32_t b1 = f2tf32(vb[4 * V_STR + 8 * nt]);
        mma_tf32(acc[nt], a0, a1, a2, a3, b0, b1);
      }
    }
  }

  // ---- epilogue ----
  float inv0 = 1.0f / l0;
  float inv1 = 1.0f / l1;
  float* o0 = Og + (size_t)(b * SEQ + qr0) * EMB + h * DHEAD;
  float* o1 = Og + (size_t)(b * SEQ + qr1) * EMB + h * DHEAD;
#pragma unroll
  for (int nt = 0; nt < 8; nt++) {
    int col = 8 * nt + 2 * c4;
    *reinterpret_cast<float2*>(o0 + col) =
        make_float2(acc[nt][0] * inv0, acc[nt][1] * inv0);
    *reinterpret_cast<float2*>(o1 + col) =
        make_float2(acc[nt][2] * inv1, acc[nt][3] * inv1);
  }
}

// ---------------------------------------------------------------------------
extern "C" void kernel_launch(void* const* d_in, const int* in_sizes, int n_in,
                              void* d_out, int out_size) {
  const float* x    = (const float*)d_in[0];
  const float* bias = (const float*)d_in[1];
  const int*   mask = (const int*)d_in[2];
  const float* Wq   = (const float*)d_in[3];
  const float* bq   = (const float*)d_in[4];
  const float* Wk   = (const float*)d_in[5];
  const float* bk   = (const float*)d_in[6];
  const float* Wv   = (const float*)d_in[7];
  const float* bv   = (const float*)d_in[8];
  const float* Wo   = (const float*)d_in[9];
  const float* bo   = (const float*)d_in[10];
  float* out = (float*)d_out;

  float *pq, *pk, *pv, *po;
  cudaGetSymbolAddress((void**)&pq, g_q);
  cudaGetSymbolAddress((void**)&pk, g_k);
  cudaGetSymbolAddress((void**)&pv, g_v);
  cudaGetSymbolAddress((void**)&po, g_o);

  cudaFuncSetAttribute(gemm_mma_kernel,
                       cudaFuncAttributeMaxDynamicSharedMemorySize, GEMM_SMEM);
  cudaFuncSetAttribute(attn_mma_kernel,
                       cudaFuncAttributeMaxDynamicSharedMemorySize, ATTN_SMEM);

  dim3 gg(BATCH * SEQ / 128, EMB / 64);  // (64, 8)
  gemm_mma_kernel<<<gg, 256, GEMM_SMEM>>>(x, Wq, bq, pq);
  gemm_mma_kernel<<<gg, 256, GEMM_SMEM>>>(x, Wk, bk, pk);
  gemm_mma_kernel<<<gg, 256, GEMM_SMEM>>>(x, Wv, bv, pv);

  dim3 ga(SEQ / 128, HEADS * BATCH);  // (32, 16)
  attn_mma_kernel<<<ga, 256, ATTN_SMEM>>>(pq, pk, pv, bias, mask, po);

  gemm_mma_kernel<<<gg, 256, GEMM_SMEM>>>(po, Wo, bo, out);
}

// round 4
// speedup vs baseline: 2.9642x; 1.1315x over previous
#include <cuda_runtime.h>
#include <cuda_bf16.h>
#include <cstdint>
#include <cstddef>

#define BATCH 2
#define SEQ   4096
#define EMB   512
#define HEADS 8
#define DHEAD 64

// Scratch (allocation-free rule: __device__ globals)
__device__ float g_q[BATCH * SEQ * EMB];
__device__ float g_k[BATCH * SEQ * EMB];
__device__ float g_v[BATCH * SEQ * EMB];
__device__ float g_o[BATCH * SEQ * EMB];

__device__ __forceinline__ uint32_t f2tf32(float f) {
  uint32_t u;
  asm("cvt.rna.tf32.f32 %0, %1;" : "=r"(u) : "f"(f));
  return u;
}

__device__ __forceinline__ void cvt4_inplace(float* p) {
  float4 v = *reinterpret_cast<float4*>(p);
  v.x = __uint_as_float(f2tf32(v.x));
  v.y = __uint_as_float(f2tf32(v.y));
  v.z = __uint_as_float(f2tf32(v.z));
  v.w = __uint_as_float(f2tf32(v.w));
  *reinterpret_cast<float4*>(p) = v;
}

__device__ __forceinline__ void mma_tf32(float c[4], uint32_t a0, uint32_t a1,
                                         uint32_t a2, uint32_t a3, uint32_t b0,
                                         uint32_t b1) {
  asm volatile(
      "mma.sync.aligned.m16n8k8.row.col.f32.tf32.tf32.f32 "
      "{%0,%1,%2,%3},{%4,%5,%6,%7},{%8,%9},{%0,%1,%2,%3};"
      : "+f"(c[0]), "+f"(c[1]), "+f"(c[2]), "+f"(c[3])
      : "r"(a0), "r"(a1), "r"(a2), "r"(a3), "r"(b0), "r"(b1));
}

__device__ __forceinline__ void cp16(uint32_t saddr, const void* gaddr) {
  asm volatile("cp.async.cg.shared.global [%0], [%1], 16;" ::"r"(saddr),
               "l"(gaddr));
}

// ---------------------------------------------------------------------------
// GEMM: Y[M,N] = X[M,K] @ W[N,K]^T + bias[N]  via mma.sync tf32.
// CTA 128x64, 8 warps. cp.async double-buffered K-chunks of 64, in-place cvt.
// ---------------------------------------------------------------------------
#define GX_STR 68
#define GW_STR 68
#define GEMM_SMEM ((2 * 128 * GX_STR + 2 * 64 * GW_STR) * (int)sizeof(float))

__global__ __launch_bounds__(256, 2) void gemm_mma_kernel(
    const float* __restrict__ X, const float* __restrict__ W,
    const float* __restrict__ bias, float* __restrict__ Y) {
  extern __shared__ float sm[];
  float* sXb = sm;                       // [2][128*GX_STR]
  float* sWb = sm + 2 * 128 * GX_STR;    // [2][64*GW_STR]

  const int Kd = EMB, Nd = EMB;
  const int m0 = blockIdx.x * 128;
  const int n0 = blockIdx.y * 64;
  const int t = threadIdx.x;
  const int w = t >> 5;
  const int lane = t & 31;
  const int r4 = lane >> 2;
  const int c4 = lane & 3;

  const uint32_t suX = (uint32_t)__cvta_generic_to_shared(sXb);
  const uint32_t suW = (uint32_t)__cvta_generic_to_shared(sWb);

  float acc[8][4];
#pragma unroll
  for (int nt = 0; nt < 8; nt++)
#pragma unroll
    for (int j = 0; j < 4; j++) acc[nt][j] = 0.f;

  // prologue: chunk 0 -> buf 0
  {
#pragma unroll
    for (int i = 0; i < 8; i++) {
      int idx = t + 256 * i;
      int r = idx >> 4;
      int c = (idx & 15) << 2;
      cp16(suX + (r * GX_STR + c) * 4, X + (size_t)(m0 + r) * Kd + c);
    }
#pragma unroll
    for (int i = 0; i < 4; i++) {
      int idx = t + 256 * i;
      int r = idx >> 4;
      int c = (idx & 15) << 2;
      cp16(suW + (r * GW_STR + c) * 4, W + (size_t)(n0 + r) * Kd + c);
    }
    asm volatile("cp.async.commit_group;" ::: "memory");
  }

  for (int kc = 0; kc < 8; kc++) {
    const int cur = kc & 1;
    float* sX = sXb + cur * 128 * GX_STR;
    float* sW = sWb + cur * 64 * GW_STR;

    __syncthreads();  // prior-iter reads of buf[nxt] done

    if (kc + 1 < 8) {
      const int nxt = cur ^ 1;
      const int koff = (kc + 1) * 64;
      const uint32_t dX = suX + nxt * 128 * GX_STR * 4;
      const uint32_t dW = suW + nxt * 64 * GW_STR * 4;
#pragma unroll
      for (int i = 0; i < 8; i++) {
        int idx = t + 256 * i;
        int r = idx >> 4;
        int c = (idx & 15) << 2;
        cp16(dX + (r * GX_STR + c) * 4, X + (size_t)(m0 + r) * Kd + koff + c);
      }
#pragma unroll
      for (int i = 0; i < 4; i++) {
        int idx = t + 256 * i;
        int r = idx >> 4;
        int c = (idx & 15) << 2;
        cp16(dW + (r * GW_STR + c) * 4, W + (size_t)(n0 + r) * Kd + koff + c);
      }
    }
    asm volatile("cp.async.commit_group;" ::: "memory");
    asm volatile("cp.async.wait_group 1;" ::: "memory");
    __syncthreads();  // buf[cur] visible to all

    // in-place tf32 conversion of buf[cur]
#pragma unroll
    for (int i = 0; i < 8; i++) {
      int idx = t + 256 * i;
      cvt4_inplace(sX + (idx >> 4) * GX_STR + ((idx & 15) << 2));
    }
#pragma unroll
    for (int i = 0; i < 4; i++) {
      int idx = t + 256 * i;
      cvt4_inplace(sW + (idx >> 4) * GW_STR + ((idx & 15) << 2));
    }
    __syncthreads();

#pragma unroll
    for (int ks = 0; ks < 8; ks++) {
      const float* ax = sX + (16 * w + r4) * GX_STR + 8 * ks + c4;
      uint32_t a0 = __float_as_uint(ax[0]);
      uint32_t a1 = __float_as_uint(ax[8 * GX_STR]);
      uint32_t a2 = __float_as_uint(ax[4]);
      uint32_t a3 = __float_as_uint(ax[8 * GX_STR + 4]);
#pragma unroll
      for (int nt = 0; nt < 8; nt++) {
        const float* bx = sW + (8 * nt + r4) * GW_STR + 8 * ks + c4;
        uint32_t b0 = __float_as_uint(bx[0]);
        uint32_t b1 = __float_as_uint(bx[4]);
        mma_tf32(acc[nt], a0, a1, a2, a3, b0, b1);
      }
    }
  }

  const int row0 = m0 + 16 * w + r4;
#pragma unroll
  for (int nt = 0; nt < 8; nt++) {
    int col = n0 + 8 * nt + 2 * c4;
    float b0 = bias[col], b1 = bias[col + 1];
    *reinterpret_cast<float2*>(Y + (size_t)row0 * Nd + col) =
        make_float2(acc[nt][0] + b0, acc[nt][1] + b1);
    *reinterpret_cast<float2*>(Y + (size_t)(row0 + 8) * Nd + col) =
        make_float2(acc[nt][2] + b0, acc[nt][3] + b1);
  }
}

// ---------------------------------------------------------------------------
// Flash attention v4: Q-frags in regs, cp.async double-buffered K/V with
// one-shot in-place tf32 conversion, fused bias+mask bounce, perm-trick PV.
// ---------------------------------------------------------------------------
#define K_STR 68
#define V_STR 72
#define B_STR 68
#define SK_FLOATS (2 * 64 * K_STR)
#define SV_FLOATS (2 * 64 * V_STR)
#define SB_FLOATS (8 * 16 * B_STR)
#define ATTN_SMEM ((SK_FLOATS + SV_FLOATS + SB_FLOATS) * (int)sizeof(float))

__global__ __launch_bounds__(256, 2) void attn_mma_kernel(
    const float* __restrict__ Qg, const float* __restrict__ Kg,
    const float* __restrict__ Vg, const float* __restrict__ bias,
    const int* __restrict__ mask, float* __restrict__ Og) {
  extern __shared__ float sm[];
  float* sK0 = sm;
  float* sV0 = sm + SK_FLOATS;
  float* sB = sm + SK_FLOATS + SV_FLOATS;

  const int q0 = blockIdx.x * 128;
  const int h = blockIdx.y >> 1;
  const int b = blockIdx.y & 1;

  const float* Qb = Qg + (size_t)b * SEQ * EMB + h * DHEAD;
  const float* Kb = Kg + (size_t)b * SEQ * EMB + h * DHEAD;
  const float* Vb = Vg + (size_t)b * SEQ * EMB + h * DHEAD;
  const float* Bb = bias + (size_t)h * SEQ * SEQ;

  const int t = threadIdx.x;
  const int w = t >> 5;
  const int lane = t & 31;
  const int r4 = lane >> 2;
  const int c4 = lane & 3;
  const int permr = ((r4 & 1) << 2) | (r4 >> 1);  // [0,4,1,5,2,6,3,7]

  // ---- stage Q raw, extract tf32 fragments to registers ----
#pragma unroll
  for (int i = 0; i < 8; i++) {
    int idx = t + 256 * i;
    int r = idx >> 4;
    int c = (idx & 15) << 2;
    float4 v = *reinterpret_cast<const float4*>(Qb + (size_t)(q0 + r) * EMB + c);
    float* d = sm + r * 68 + c;
    d[0] = v.x; d[1] = v.y; d[2] = v.z; d[3] = v.w;
  }
  __syncthreads();
  uint32_t qa[8][4];
#pragma unroll
  for (int ks = 0; ks < 8; ks++) {
    const float* ax = sm + (16 * w + r4) * 68 + 8 * ks + c4;
    qa[ks][0] = f2tf32(ax[0]);
    qa[ks][1] = f2tf32(ax[8 * 68]);
    qa[ks][2] = f2tf32(ax[4]);
    qa[ks][3] = f2tf32(ax[8 * 68 + 4]);
  }
  __syncthreads();

  const int qr0 = q0 + 16 * w + r4;
  const int qr1 = qr0 + 8;
  float* sBw = sB + w * 16 * B_STR;

  float m0 = -1e30f, m1 = -1e30f, l0 = 0.f, l1 = 0.f;
  float acc[8][4];
#pragma unroll
  for (int nt = 0; nt < 8; nt++)
#pragma unroll
    for (int j = 0; j < 4; j++) acc[nt][j] = 0.f;

  const uint32_t suK = (uint32_t)__cvta_generic_to_shared(sK0);
  const uint32_t suV = (uint32_t)__cvta_generic_to_shared(sV0);

  // prologue: tile 0 -> buf 0
  {
#pragma unroll
    for (int i = 0; i < 4; i++) {
      int idx = t + 256 * i;
      int r = idx >> 4;
      int c = (idx & 15) << 2;
      cp16(suK + (r * K_STR + c) * 4, Kb + (size_t)r * EMB + c);
      cp16(suV + (r * V_STR + c) * 4, Vb + (size_t)r * EMB + c);
    }
    asm volatile("cp.async.commit_group;" ::: "memory");
  }

  for (int kt = 0; kt < 64; kt++) {
    const int cur = kt & 1;
    float* sKc = sK0 + cur * 64 * K_STR;
    float* sVc = sV0 + cur * 64 * V_STR;

    __syncthreads();  // prior-iter reads of buf[nxt] and sB complete

    if (kt + 1 < 64) {
      const int nxt = cur ^ 1;
      const float* Ksrc = Kb + (size_t)(kt + 1) * 64 * EMB;
      const float* Vsrc = Vb + (size_t)(kt + 1) * 64 * EMB;
      const uint32_t dK = suK + nxt * 64 * K_STR * 4;
      const uint32_t dV = suV + nxt * 64 * V_STR * 4;
#pragma unroll
      for (int i = 0; i < 4; i++) {
        int idx = t + 256 * i;
        int r = idx >> 4;
        int c = (idx & 15) << 2;
        cp16(dK + (r * K_STR + c) * 4, Ksrc + (size_t)r * EMB + c);
        cp16(dV + (r * V_STR + c) * 4, Vsrc + (size_t)r * EMB + c);
      }
    }
    asm volatile("cp.async.commit_group;" ::: "memory");

    // ---- fused bias+mask bounce (overlaps cp.async latency) ----
    {
      const int k0 = kt * 64;
      const int hl = lane >> 4;
      const int cl = (lane & 15) << 2;
#pragma unroll
      for (int i = 0; i < 8; i++) {
        int rl = 2 * i + hl;
        size_t off = (size_t)(q0 + 16 * w + rl) * SEQ + k0 + cl;
        float4 bv = *reinterpret_cast<const float4*>(Bb + off);
        int4 mv = *reinterpret_cast<const int4*>(mask + off);
        float4 f;
        f.x = mv.x ? bv.x : -1e20f;
        f.y = mv.y ? bv.y : -1e20f;
        f.z = mv.z ? bv.z : -1e20f;
        f.w = mv.w ? bv.w : -1e20f;
        *reinterpret_cast<float4*>(sBw + rl * B_STR + cl) = f;
      }
    }

    asm volatile("cp.async.wait_group 1;" ::: "memory");
    __syncthreads();  // K/V buf[cur] visible

    // ---- one-shot in-place tf32 conversion of K/V tile ----
#pragma unroll
    for (int i = 0; i < 4; i++) {
      int idx = t + 256 * i;
      int r = idx >> 4;
      int c = (idx & 15) << 2;
      cvt4_inplace(sKc + r * K_STR + c);
      cvt4_inplace(sVc + r * V_STR + c);
    }
    __syncthreads();

    // ---- S = Q @ K^T (permuted cols), no per-fragment cvt ----
    float S[8][4];
#pragma unroll
    for (int nt = 0; nt < 8; nt++)
#pragma unroll
      for (int j = 0; j < 4; j++) S[nt][j] = 0.f;

#pragma unroll
    for (int ks = 0; ks < 8; ks++) {
      const float* kb = sKc + permr * K_STR + 8 * ks + c4;
      uint32_t a0 = qa[ks][0], a1 = qa[ks][1], a2 = qa[ks][2], a3 = qa[ks][3];
#pragma unroll
      for (int nt = 0; nt < 8; nt++) {
        uint32_t b0 = __float_as_uint(kb[8 * nt * K_STR]);
        uint32_t b1 = __float_as_uint(kb[8 * nt * K_STR + 4]);
        mma_tf32(S[nt], a0, a1, a2, a3, b0, b1);
      }
    }

    // ---- apply fused bias, scale, row max ----
    float mx0 = -1e30f, mx1 = -1e30f;
#pragma unroll
    for (int nt = 0; nt < 8; nt++) {
      int cc = 8 * nt + c4;
      float f0 = sBw[r4 * B_STR + cc];
      float f1 = sBw[r4 * B_STR + cc + 4];
      float f2 = sBw[(r4 + 8) * B_STR + cc];
      float f3 = sBw[(r4 + 8) * B_STR + cc + 4];
      float s0 = (S[nt][0] + f0) * 0.125f;
      float s1 = (S[nt][1] + f1) * 0.125f;
      float s2 = (S[nt][2] + f2) * 0.125f;
      float s3 = (S[nt][3] + f3) * 0.125f;
      S[nt][0] = s0; S[nt][1] = s1; S[nt][2] = s2; S[nt][3] = s3;
      mx0 = fmaxf(mx0, fmaxf(s0, s1));
      mx1 = fmaxf(mx1, fmaxf(s2, s3));
    }
    mx0 = fmaxf(mx0, __shfl_xor_sync(0xffffffffu, mx0, 1));
    mx0 = fmaxf(mx0, __shfl_xor_sync(0xffffffffu, mx0, 2));
    mx1 = fmaxf(mx1, __shfl_xor_sync(0xffffffffu, mx1, 1));
    mx1 = fmaxf(mx1, __shfl_xor_sync(0xffffffffu, mx1, 2));

    float mn0 = fmaxf(m0, mx0);
    float mn1 = fmaxf(m1, mx1);
    float corr0 = __expf(m0 - mn0);
    float corr1 = __expf(m1 - mn1);
    m0 = mn0; m1 = mn1;

    float sum0 = 0.f, sum1 = 0.f;
#pragma unroll
    for (int nt = 0; nt < 8; nt++) {
      float p0 = __expf(S[nt][0] - mn0);
      float p1 = __expf(S[nt][1] - mn0);
      float p2 = __expf(S[nt][2] - mn1);
      float p3 = __expf(S[nt][3] - mn1);
      S[nt][0] = p0; S[nt][1] = p1; S[nt][2] = p2; S[nt][3] = p3;
      sum0 += p0 + p1;
      sum1 += p2 + p3;
    }
    sum0 += __shfl_xor_sync(0xffffffffu, sum0, 1);
    sum0 += __shfl_xor_sync(0xffffffffu, sum0, 2);
    sum1 += __shfl_xor_sync(0xffffffffu, sum1, 1);
    sum1 += __shfl_xor_sync(0xffffffffu, sum1, 2);
    l0 = l0 * corr0 + sum0;
    l1 = l1 * corr1 + sum1;

#pragma unroll
    for (int nt = 0; nt < 8; nt++) {
      acc[nt][0] *= corr0; acc[nt][1] *= corr0;
      acc[nt][2] *= corr1; acc[nt][3] *= corr1;
    }

    // ---- PV: A from S regs (perm trick) ----
#pragma unroll
    for (int t8 = 0; t8 < 8; t8++) {
      uint32_t a0 = f2tf32(S[t8][0]);
      uint32_t a1 = f2tf32(S[t8][2]);
      uint32_t a2 = f2tf32(S[t8][1]);
      uint32_t a3 = f2tf32(S[t8][3]);
      const float* vb = sVc + (8 * t8 + c4) * V_STR + r4;
#pragma unroll
      for (int nt = 0; nt < 8; nt++) {
        uint32_t b0 = __float_as_uint(vb[8 * nt]);
        uint32_t b1 = __float_as_uint(vb[4 * V_STR + 8 * nt]);
        mma_tf32(acc[nt], a0, a1, a2, a3, b0, b1);
      }
    }
  }

  // ---- epilogue ----
  float inv0 = 1.0f / l0;
  float inv1 = 1.0f / l1;
  float* o0 = Og + (size_t)(b * SEQ + qr0) * EMB + h * DHEAD;
  float* o1 = Og + (size_t)(b * SEQ + qr1) * EMB + h * DHEAD;
#pragma unroll
  for (int nt = 0; nt < 8; nt++) {
    int col = 8 * nt + 2 * c4;
    *reinterpret_cast<float2*>(o0 + col) =
        make_float2(acc[nt][0] * inv0, acc[nt][1] * inv0);
    *reinterpret_cast<float2*>(o1 + col) =
        make_float2(acc[nt][2] * inv1, acc[nt][3] * inv1);
  }
}

// ---------------------------------------------------------------------------
extern "C" void kernel_launch(void* const* d_in, const int* in_sizes, int n_in,
                              void* d_out, int out_size) {
  const float* x    = (const float*)d_in[0];
  const float* bias = (const float*)d_in[1];
  const int*   mask = (const int*)d_in[2];
  const float* Wq   = (const float*)d_in[3];
  const float* bq   = (const float*)d_in[4];
  const float* Wk   = (const float*)d_in[5];
  const float* bk   = (const float*)d_in[6];
  const float* Wv   = (const float*)d_in[7];
  const float* bv   = (const float*)d_in[8];
  const float* Wo   = (const float*)d_in[9];
  const float* bo   = (const float*)d_in[10];
  float* out = (float*)d_out;

  float *pq, *pk, *pv, *po;
  cudaGetSymbolAddress((void**)&pq, g_q);
  cudaGetSymbolAddress((void**)&pk, g_k);
  cudaGetSymbolAddress((void**)&pv, g_v);
  cudaGetSymbolAddress((void**)&po, g_o);

  cudaFuncSetAttribute(gemm_mma_kernel,
                       cudaFuncAttributeMaxDynamicSharedMemorySize, GEMM_SMEM);
  cudaFuncSetAttribute(attn_mma_kernel,
                       cudaFuncAttributeMaxDynamicSharedMemorySize, ATTN_SMEM);

  dim3 gg(BATCH * SEQ / 128, EMB / 64);  // (64, 8)
  gemm_mma_kernel<<<gg, 256, GEMM_SMEM>>>(x, Wq, bq, pq);
  gemm_mma_kernel<<<gg, 256, GEMM_SMEM>>>(x, Wk, bk, pk);
  gemm_mma_kernel<<<gg, 256, GEMM_SMEM>>>(x, Wv, bv, pv);

  dim3 ga(SEQ / 128, HEADS * BATCH);  // (32, 16)
  attn_mma_kernel<<<ga, 256, ATTN_SMEM>>>(pq, pk, pv, bias, mask, po);

  gemm_mma_kernel<<<gg, 256, GEMM_SMEM>>>(po, Wo, bo, out);
}

// round 5
// speedup vs baseline: 3.3379x; 1.1261x over previous
#include <cuda_runtime.h>
#include <cuda_bf16.h>
#include <cstdint>
#include <cstddef>

#define BATCH 2
#define SEQ   4096
#define EMB   512
#define HEADS 8
#define DHEAD 64

// Scratch (allocation-free rule: __device__ globals)
__device__ float g_q[BATCH * SEQ * EMB];
__device__ float g_k[BATCH * SEQ * EMB];
__device__ float g_v[BATCH * SEQ * EMB];
__device__ float g_o[BATCH * SEQ * EMB];
__device__ float g_x[BATCH * SEQ * EMB];
__device__ float g_wq[EMB * EMB];
__device__ float g_wk[EMB * EMB];
__device__ float g_wv[EMB * EMB];
__device__ float g_wo[EMB * EMB];

__device__ __forceinline__ uint32_t f2tf32(float f) {
  uint32_t u;
  asm("cvt.rna.tf32.f32 %0, %1;" : "=r"(u) : "f"(f));
  return u;
}

__device__ __forceinline__ void mma_tf32(float c[4], uint32_t a0, uint32_t a1,
                                         uint32_t a2, uint32_t a3, uint32_t b0,
                                         uint32_t b1) {
  asm volatile(
      "mma.sync.aligned.m16n8k8.row.col.f32.tf32.tf32.f32 "
      "{%0,%1,%2,%3},{%4,%5,%6,%7},{%8,%9},{%0,%1,%2,%3};"
      : "+f"(c[0]), "+f"(c[1]), "+f"(c[2]), "+f"(c[3])
      : "r"(a0), "r"(a1), "r"(a2), "r"(a3), "r"(b0), "r"(b1));
}

__device__ __forceinline__ void cp16(uint32_t saddr, const void* gaddr) {
  asm volatile("cp.async.cg.shared.global [%0], [%1], 16;" ::"r"(saddr),
               "l"(gaddr));
}

// ---------------------------------------------------------------------------
// Elementwise tf32 pre-rounding (producer-side conversion).
// ---------------------------------------------------------------------------
__global__ __launch_bounds__(256) void round_tf32_kernel(
    const float* __restrict__ in, float* __restrict__ out, int n4) {
  int i = blockIdx.x * 256 + threadIdx.x;
  if (i < n4) {
    float4 v = reinterpret_cast<const float4*>(in)[i];
    v.x = __uint_as_float(f2tf32(v.x));
    v.y = __uint_as_float(f2tf32(v.y));
    v.z = __uint_as_float(f2tf32(v.z));
    v.w = __uint_as_float(f2tf32(v.w));
    reinterpret_cast<float4*>(out)[i] = v;
  }
}

// ---------------------------------------------------------------------------
// GEMM: Y[M,N] = X[M,K] @ W[N,K]^T + bias[N] via mma.sync tf32.
// Inputs pre-rounded to tf32 (no cvt pass). cp.async double-buffered.
// ROUND_OUT: round the result to tf32 for downstream tf32 consumers.
// ---------------------------------------------------------------------------
#define GX_STR 68
#define GW_STR 68
#define GEMM_SMEM ((2 * 128 * GX_STR + 2 * 64 * GW_STR) * (int)sizeof(float))

template <bool ROUND_OUT>
__global__ __launch_bounds__(256, 2) void gemm_mma_kernel(
    const float* __restrict__ X, const float* __restrict__ W,
    const float* __restrict__ bias, float* __restrict__ Y) {
  extern __shared__ float sm[];
  float* sXb = sm;
  float* sWb = sm + 2 * 128 * GX_STR;

  const int Kd = EMB, Nd = EMB;
  const int m0 = blockIdx.x * 128;
  const int n0 = blockIdx.y * 64;
  const int t = threadIdx.x;
  const int w = t >> 5;
  const int lane = t & 31;
  const int r4 = lane >> 2;
  const int c4 = lane & 3;

  const uint32_t suX = (uint32_t)__cvta_generic_to_shared(sXb);
  const uint32_t suW = (uint32_t)__cvta_generic_to_shared(sWb);

  float acc[8][4];
#pragma unroll
  for (int nt = 0; nt < 8; nt++)
#pragma unroll
    for (int j = 0; j < 4; j++) acc[nt][j] = 0.f;

  // prologue: chunk 0 -> buf 0
  {
#pragma unroll
    for (int i = 0; i < 8; i++) {
      int idx = t + 256 * i;
      int r = idx >> 4;
      int c = (idx & 15) << 2;
      cp16(suX + (r * GX_STR + c) * 4, X + (size_t)(m0 + r) * Kd + c);
    }
#pragma unroll
    for (int i = 0; i < 4; i++) {
      int idx = t + 256 * i;
      int r = idx >> 4;
      int c = (idx & 15) << 2;
      cp16(suW + (r * GW_STR + c) * 4, W + (size_t)(n0 + r) * Kd + c);
    }
    asm volatile("cp.async.commit_group;" ::: "memory");
  }

  for (int kc = 0; kc < 8; kc++) {
    const int cur = kc & 1;
    const float* sX = sXb + cur * 128 * GX_STR;
    const float* sW = sWb + cur * 64 * GW_STR;

    __syncthreads();  // prior-iter reads of buf[nxt] done

    if (kc + 1 < 8) {
      const int nxt = cur ^ 1;
      const int koff = (kc + 1) * 64;
      const uint32_t dX = suX + nxt * 128 * GX_STR * 4;
      const uint32_t dW = suW + nxt * 64 * GW_STR * 4;
#pragma unroll
      for (int i = 0; i < 8; i++) {
        int idx = t + 256 * i;
        int r = idx >> 4;
        int c = (idx & 15) << 2;
        cp16(dX + (r * GX_STR + c) * 4, X + (size_t)(m0 + r) * Kd + koff + c);
      }
#pragma unroll
      for (int i = 0; i < 4; i++) {
        int idx = t + 256 * i;
        int r = idx >> 4;
        int c = (idx & 15) << 2;
        cp16(dW + (r * GW_STR + c) * 4, W + (size_t)(n0 + r) * Kd + koff + c);
      }
    }
    asm volatile("cp.async.commit_group;" ::: "memory");
    asm volatile("cp.async.wait_group 1;" ::: "memory");
    __syncthreads();  // buf[cur] visible

#pragma unroll
    for (int ks = 0; ks < 8; ks++) {
      const float* ax = sX + (16 * w + r4) * GX_STR + 8 * ks + c4;
      uint32_t a0 = __float_as_uint(ax[0]);
      uint32_t a1 = __float_as_uint(ax[8 * GX_STR]);
      uint32_t a2 = __float_as_uint(ax[4]);
      uint32_t a3 = __float_as_uint(ax[8 * GX_STR + 4]);
#pragma unroll
      for (int nt = 0; nt < 8; nt++) {
        const float* bx = sW + (8 * nt + r4) * GW_STR + 8 * ks + c4;
        uint32_t b0 = __float_as_uint(bx[0]);
        uint32_t b1 = __float_as_uint(bx[4]);
        mma_tf32(acc[nt], a0, a1, a2, a3, b0, b1);
      }
    }
  }

  const int row0 = m0 + 16 * w + r4;
#pragma unroll
  for (int nt = 0; nt < 8; nt++) {
    int col = n0 + 8 * nt + 2 * c4;
    float b0 = bias[col], b1 = bias[col + 1];
    float y00 = acc[nt][0] + b0, y01 = acc[nt][1] + b1;
    float y10 = acc[nt][2] + b0, y11 = acc[nt][3] + b1;
    if (ROUND_OUT) {
      y00 = __uint_as_float(f2tf32(y00));
      y01 = __uint_as_float(f2tf32(y01));
      y10 = __uint_as_float(f2tf32(y10));
      y11 = __uint_as_float(f2tf32(y11));
    }
    *reinterpret_cast<float2*>(Y + (size_t)row0 * Nd + col) =
        make_float2(y00, y01);
    *reinterpret_cast<float2*>(Y + (size_t)(row0 + 8) * Nd + col) =
        make_float2(y10, y11);
  }
}

// ---------------------------------------------------------------------------
// Flash attention v5: K/V pre-rounded tf32 (no cvt pass, 2 barriers/tile),
// Q-frags in regs, cp.async double-buffered K/V, fused bias+mask bounce,
// perm-trick PV. Output rounded to tf32 for the O-projection GEMM.
// ---------------------------------------------------------------------------
#define K_STR 68
#define V_STR 72
#define B_STR 68
#define SK_FLOATS (2 * 64 * K_STR)
#define SV_FLOATS (2 * 64 * V_STR)
#define SB_FLOATS (8 * 16 * B_STR)
#define ATTN_SMEM ((SK_FLOATS + SV_FLOATS + SB_FLOATS) * (int)sizeof(float))

__global__ __launch_bounds__(256, 2) void attn_mma_kernel(
    const float* __restrict__ Qg, const float* __restrict__ Kg,
    const float* __restrict__ Vg, const float* __restrict__ bias,
    const int* __restrict__ mask, float* __restrict__ Og) {
  extern __shared__ float sm[];
  float* sK0 = sm;
  float* sV0 = sm + SK_FLOATS;
  float* sB = sm + SK_FLOATS + SV_FLOATS;

  const int q0 = blockIdx.x * 128;
  const int h = blockIdx.y >> 1;
  const int b = blockIdx.y & 1;

  const float* Qb = Qg + (size_t)b * SEQ * EMB + h * DHEAD;
  const float* Kb = Kg + (size_t)b * SEQ * EMB + h * DHEAD;
  const float* Vb = Vg + (size_t)b * SEQ * EMB + h * DHEAD;
  const float* Bb = bias + (size_t)h * SEQ * SEQ;

  const int t = threadIdx.x;
  const int w = t >> 5;
  const int lane = t & 31;
  const int r4 = lane >> 2;
  const int c4 = lane & 3;
  const int permr = ((r4 & 1) << 2) | (r4 >> 1);  // [0,4,1,5,2,6,3,7]

  // ---- stage Q (already tf32-rounded), extract fragments to registers ----
#pragma unroll
  for (int i = 0; i < 8; i++) {
    int idx = t + 256 * i;
    int r = idx >> 4;
    int c = (idx & 15) << 2;
    float4 v = *reinterpret_cast<const float4*>(Qb + (size_t)(q0 + r) * EMB + c);
    float* d = sm + r * 68 + c;
    d[0] = v.x; d[1] = v.y; d[2] = v.z; d[3] = v.w;
  }
  __syncthreads();
  uint32_t qa[8][4];
#pragma unroll
  for (int ks = 0; ks < 8; ks++) {
    const float* ax = sm + (16 * w + r4) * 68 + 8 * ks + c4;
    qa[ks][0] = __float_as_uint(ax[0]);
    qa[ks][1] = __float_as_uint(ax[8 * 68]);
    qa[ks][2] = __float_as_uint(ax[4]);
    qa[ks][3] = __float_as_uint(ax[8 * 68 + 4]);
  }
  __syncthreads();

  const int qr0 = q0 + 16 * w + r4;
  const int qr1 = qr0 + 8;
  float* sBw = sB + w * 16 * B_STR;

  float m0 = -1e30f, m1 = -1e30f, l0 = 0.f, l1 = 0.f;
  float acc[8][4];
#pragma unroll
  for (int nt = 0; nt < 8; nt++)
#pragma unroll
    for (int j = 0; j < 4; j++) acc[nt][j] = 0.f;

  const uint32_t suK = (uint32_t)__cvta_generic_to_shared(sK0);
  const uint32_t suV = (uint32_t)__cvta_generic_to_shared(sV0);

  // prologue: tile 0 -> buf 0
  {
#pragma unroll
    for (int i = 0; i < 4; i++) {
      int idx = t + 256 * i;
      int r = idx >> 4;
      int c = (idx & 15) << 2;
      cp16(suK + (r * K_STR + c) * 4, Kb + (size_t)r * EMB + c);
      cp16(suV + (r * V_STR + c) * 4, Vb + (size_t)r * EMB + c);
    }
    asm volatile("cp.async.commit_group;" ::: "memory");
  }

  for (int kt = 0; kt < 64; kt++) {
    const int cur = kt & 1;
    const float* sKc = sK0 + cur * 64 * K_STR;
    const float* sVc = sV0 + cur * 64 * V_STR;

    __syncthreads();  // prior-iter reads of buf[nxt] and sB complete

    if (kt + 1 < 64) {
      const int nxt = cur ^ 1;
      const float* Ksrc = Kb + (size_t)(kt + 1) * 64 * EMB;
      const float* Vsrc = Vb + (size_t)(kt + 1) * 64 * EMB;
      const uint32_t dK = suK + nxt * 64 * K_STR * 4;
      const uint32_t dV = suV + nxt * 64 * V_STR * 4;
#pragma unroll
      for (int i = 0; i < 4; i++) {
        int idx = t + 256 * i;
        int r = idx >> 4;
        int c = (idx & 15) << 2;
        cp16(dK + (r * K_STR + c) * 4, Ksrc + (size_t)r * EMB + c);
        cp16(dV + (r * V_STR + c) * 4, Vsrc + (size_t)r * EMB + c);
      }
    }
    asm volatile("cp.async.commit_group;" ::: "memory");

    // ---- fused bias+mask bounce (overlaps cp.async latency) ----
    {
      const int k0 = kt * 64;
      const int hl = lane >> 4;
      const int cl = (lane & 15) << 2;
#pragma unroll
      for (int i = 0; i < 8; i++) {
        int rl = 2 * i + hl;
        size_t off = (size_t)(q0 + 16 * w + rl) * SEQ + k0 + cl;
        float4 bv = *reinterpret_cast<const float4*>(Bb + off);
        int4 mv = *reinterpret_cast<const int4*>(mask + off);
        float4 f;
        f.x = mv.x ? bv.x : -1e20f;
        f.y = mv.y ? bv.y : -1e20f;
        f.z = mv.z ? bv.z : -1e20f;
        f.w = mv.w ? bv.w : -1e20f;
        *reinterpret_cast<float4*>(sBw + rl * B_STR + cl) = f;
      }
    }

    asm volatile("cp.async.wait_group 1;" ::: "memory");
    __syncthreads();  // K/V buf[cur] (already tf32) + sB visible

    // ---- S = Q @ K^T (permuted cols) ----
    float S[8][4];
#pragma unroll
    for (int nt = 0; nt < 8; nt++)
#pragma unroll
      for (int j = 0; j < 4; j++) S[nt][j] = 0.f;

#pragma unroll
    for (int ks = 0; ks < 8; ks++) {
      const float* kb = sKc + permr * K_STR + 8 * ks + c4;
      uint32_t a0 = qa[ks][0], a1 = qa[ks][1], a2 = qa[ks][2], a3 = qa[ks][3];
#pragma unroll
      for (int nt = 0; nt < 8; nt++) {
        uint32_t b0 = __float_as_uint(kb[8 * nt * K_STR]);
        uint32_t b1 = __float_as_uint(kb[8 * nt * K_STR + 4]);
        mma_tf32(S[nt], a0, a1, a2, a3, b0, b1);
      }
    }

    // ---- apply fused bias, scale, row max ----
    float mx0 = -1e30f, mx1 = -1e30f;
#pragma unroll
    for (int nt = 0; nt < 8; nt++) {
      int cc = 8 * nt + c4;
      float f0 = sBw[r4 * B_STR + cc];
      float f1 = sBw[r4 * B_STR + cc + 4];
      float f2 = sBw[(r4 + 8) * B_STR + cc];
      float f3 = sBw[(r4 + 8) * B_STR + cc + 4];
      float s0 = (S[nt][0] + f0) * 0.125f;
      float s1 = (S[nt][1] + f1) * 0.125f;
      float s2 = (S[nt][2] + f2) * 0.125f;
      float s3 = (S[nt][3] + f3) * 0.125f;
      S[nt][0] = s0; S[nt][1] = s1; S[nt][2] = s2; S[nt][3] = s3;
      mx0 = fmaxf(mx0, fmaxf(s0, s1));
      mx1 = fmaxf(mx1, fmaxf(s2, s3));
    }
    mx0 = fmaxf(mx0, __shfl_xor_sync(0xffffffffu, mx0, 1));
    mx0 = fmaxf(mx0, __shfl_xor_sync(0xffffffffu, mx0, 2));
    mx1 = fmaxf(mx1, __shfl_xor_sync(0xffffffffu, mx1, 1));
    mx1 = fmaxf(mx1, __shfl_xor_sync(0xffffffffu, mx1, 2));

    float mn0 = fmaxf(m0, mx0);
    float mn1 = fmaxf(m1, mx1);
    float corr0 = __expf(m0 - mn0);
    float corr1 = __expf(m1 - mn1);
    m0 = mn0; m1 = mn1;

    float sum0 = 0.f, sum1 = 0.f;
#pragma unroll
    for (int nt = 0; nt < 8; nt++) {
      float p0 = __expf(S[nt][0] - mn0);
      float p1 = __expf(S[nt][1] - mn0);
      float p2 = __expf(S[nt][2] - mn1);
      float p3 = __expf(S[nt][3] - mn1);
      S[nt][0] = p0; S[nt][1] = p1; S[nt][2] = p2; S[nt][3] = p3;
      sum0 += p0 + p1;
      sum1 += p2 + p3;
    }
    sum0 += __shfl_xor_sync(0xffffffffu, sum0, 1);
    sum0 += __shfl_xor_sync(0xffffffffu, sum0, 2);
    sum1 += __shfl_xor_sync(0xffffffffu, sum1, 1);
    sum1 += __shfl_xor_sync(0xffffffffu, sum1, 2);
    l0 = l0 * corr0 + sum0;
    l1 = l1 * corr1 + sum1;

#pragma unroll
    for (int nt = 0; nt < 8; nt++) {
      acc[nt][0] *= corr0; acc[nt][1] *= corr0;
      acc[nt][2] *= corr1; acc[nt][3] *= corr1;
    }

    // ---- PV: A from S regs (perm trick) ----
#pragma unroll
    for (int t8 = 0; t8 < 8; t8++) {
      uint32_t a0 = f2tf32(S[t8][0]);
      uint32_t a1 = f2tf32(S[t8][2]);
      uint32_t a2 = f2tf32(S[t8][1]);
      uint32_t a3 = f2tf32(S[t8][3]);
      const float* vb = sVc + (8 * t8 + c4) * V_STR + r4;
#pragma unroll
      for (int nt = 0; nt < 8; nt++) {
        uint32_t b0 = __float_as_uint(vb[8 * nt]);
        uint32_t b1 = __float_as_uint(vb[4 * V_STR + 8 * nt]);
        mma_tf32(acc[nt], a0, a1, a2, a3, b0, b1);
      }
    }
  }

  // ---- epilogue: round O to tf32 (consumed by tf32 O-projection) ----
  float inv0 = 1.0f / l0;
  float inv1 = 1.0f / l1;
  float* o0 = Og + (size_t)(b * SEQ + qr0) * EMB + h * DHEAD;
  float* o1 = Og + (size_t)(b * SEQ + qr1) * EMB + h * DHEAD;
#pragma unroll
  for (int nt = 0; nt < 8; nt++) {
    int col = 8 * nt + 2 * c4;
    *reinterpret_cast<float2*>(o0 + col) =
        make_float2(__uint_as_float(f2tf32(acc[nt][0] * inv0)),
                    __uint_as_float(f2tf32(acc[nt][1] * inv0)));
    *reinterpret_cast<float2*>(o1 + col) =
        make_float2(__uint_as_float(f2tf32(acc[nt][2] * inv1)),
                    __uint_as_float(f2tf32(acc[nt][3] * inv1)));
  }
}

// ---------------------------------------------------------------------------
extern "C" void kernel_launch(void* const* d_in, const int* in_sizes, int n_in,
                              void* d_out, int out_size) {
  const float* x    = (const float*)d_in[0];
  const float* bias = (const float*)d_in[1];
  const int*   mask = (const int*)d_in[2];
  const float* Wq   = (const float*)d_in[3];
  const float* bq   = (const float*)d_in[4];
  const float* Wk   = (const float*)d_in[5];
  const float* bk   = (const float*)d_in[6];
  const float* Wv   = (const float*)d_in[7];
  const float* bv   = (const float*)d_in[8];
  const float* Wo   = (const float*)d_in[9];
  const float* bo   = (const float*)d_in[10];
  float* out = (float*)d_out;

  float *pq, *pk, *pv, *po, *px, *pwq, *pwk, *pwv, *pwo;
  cudaGetSymbolAddress((void**)&pq, g_q);
  cudaGetSymbolAddress((void**)&pk, g_k);
  cudaGetSymbolAddress((void**)&pv, g_v);
  cudaGetSymbolAddress((void**)&po, g_o);
  cudaGetSymbolAddress((void**)&px, g_x);
  cudaGetSymbolAddress((void**)&pwq, g_wq);
  cudaGetSymbolAddress((void**)&pwk, g_wk);
  cudaGetSymbolAddress((void**)&pwv, g_wv);
  cudaGetSymbolAddress((void**)&pwo, g_wo);

  cudaFuncSetAttribute(gemm_mma_kernel<true>,
                       cudaFuncAttributeMaxDynamicSharedMemorySize, GEMM_SMEM);
  cudaFuncSetAttribute(gemm_mma_kernel<false>,
                       cudaFuncAttributeMaxDynamicSharedMemorySize, GEMM_SMEM);
  cudaFuncSetAttribute(attn_mma_kernel,
                       cudaFuncAttributeMaxDynamicSharedMemorySize, ATTN_SMEM);

  // producer-side tf32 rounding of x and weights
  const int nx4 = BATCH * SEQ * EMB / 4;   // 1,048,576
  const int nw4 = EMB * EMB / 4;           // 65,536
  round_tf32_kernel<<<(nx4 + 255) / 256, 256>>>(x, px, nx4);
  round_tf32_kernel<<<(nw4 + 255) / 256, 256>>>(Wq, pwq, nw4);
  round_tf32_kernel<<<(nw4 + 255) / 256, 256>>>(Wk, pwk, nw4);
  round_tf32_kernel<<<(nw4 + 255) / 256, 256>>>(Wv, pwv, nw4);
  round_tf32_kernel<<<(nw4 + 255) / 256, 256>>>(Wo, pwo, nw4);

  dim3 gg(BATCH * SEQ / 128, EMB / 64);  // (64, 8)
  gemm_mma_kernel<true><<<gg, 256, GEMM_SMEM>>>(px, pwq, bq, pq);
  gemm_mma_kernel<true><<<gg, 256, GEMM_SMEM>>>(px, pwk, bk, pk);
  gemm_mma_kernel<true><<<gg, 256, GEMM_SMEM>>>(px, pwv, bv, pv);

  dim3 ga(SEQ / 128, HEADS * BATCH);  // (32, 16)
  attn_mma_kernel<<<ga, 256, ATTN_SMEM>>>(pq, pk, pv, bias, mask, po);

  gemm_mma_kernel<false><<<gg, 256, GEMM_SMEM>>>(po, pwo, bo, out);
}

// round 6
// speedup vs baseline: 3.3468x; 1.0027x over previous
#include <cuda_runtime.h>
#include <cuda_bf16.h>
#include <cstdint>
#include <cstddef>

#define BATCH 2
#define SEQ   4096
#define EMB   512
#define HEADS 8
#define DHEAD 64

// Scratch (allocation-free rule: __device__ globals)
__device__ float g_q[BATCH * SEQ * EMB];
__device__ float g_k[BATCH * SEQ * EMB];
__device__ float g_v[BATCH * SEQ * EMB];
__device__ float g_o[BATCH * SEQ * EMB];
__device__ float g_x[BATCH * SEQ * EMB];
__device__ float g_wq[EMB * EMB];
__device__ float g_wk[EMB * EMB];
__device__ float g_wv[EMB * EMB];
__device__ float g_wo[EMB * EMB];

__device__ __forceinline__ uint32_t f2tf32(float f) {
  uint32_t u;
  asm("cvt.rna.tf32.f32 %0, %1;" : "=r"(u) : "f"(f));
  return u;
}

__device__ __forceinline__ void mma_tf32(float c[4], uint32_t a0, uint32_t a1,
                                         uint32_t a2, uint32_t a3, uint32_t b0,
                                         uint32_t b1) {
  asm volatile(
      "mma.sync.aligned.m16n8k8.row.col.f32.tf32.tf32.f32 "
      "{%0,%1,%2,%3},{%4,%5,%6,%7},{%8,%9},{%0,%1,%2,%3};"
      : "+f"(c[0]), "+f"(c[1]), "+f"(c[2]), "+f"(c[3])
      : "r"(a0), "r"(a1), "r"(a2), "r"(a3), "r"(b0), "r"(b1));
}

__device__ __forceinline__ void cp16(uint32_t saddr, const void* gaddr) {
  asm volatile("cp.async.cg.shared.global [%0], [%1], 16;" ::"r"(saddr),
               "l"(gaddr));
}

// ---------------------------------------------------------------------------
// Elementwise tf32 pre-rounding (producer-side conversion).
// ---------------------------------------------------------------------------
__global__ __launch_bounds__(256) void round_tf32_kernel(
    const float* __restrict__ in, float* __restrict__ out, int n4) {
  int i = blockIdx.x * 256 + threadIdx.x;
  if (i < n4) {
    float4 v = reinterpret_cast<const float4*>(in)[i];
    v.x = __uint_as_float(f2tf32(v.x));
    v.y = __uint_as_float(f2tf32(v.y));
    v.z = __uint_as_float(f2tf32(v.z));
    v.w = __uint_as_float(f2tf32(v.w));
    reinterpret_cast<float4*>(out)[i] = v;
  }
}

// ---------------------------------------------------------------------------
// GEMM: Y[M,N] = X[M,K] @ W[N,K]^T + bias[N] via mma.sync tf32 (R5, unchanged).
// ---------------------------------------------------------------------------
#define GX_STR 68
#define GW_STR 68
#define GEMM_SMEM ((2 * 128 * GX_STR + 2 * 64 * GW_STR) * (int)sizeof(float))

template <bool ROUND_OUT>
__global__ __launch_bounds__(256, 2) void gemm_mma_kernel(
    const float* __restrict__ X, const float* __restrict__ W,
    const float* __restrict__ bias, float* __restrict__ Y) {
  extern __shared__ float sm[];
  float* sXb = sm;
  float* sWb = sm + 2 * 128 * GX_STR;

  const int Kd = EMB, Nd = EMB;
  const int m0 = blockIdx.x * 128;
  const int n0 = blockIdx.y * 64;
  const int t = threadIdx.x;
  const int w = t >> 5;
  const int lane = t & 31;
  const int r4 = lane >> 2;
  const int c4 = lane & 3;

  const uint32_t suX = (uint32_t)__cvta_generic_to_shared(sXb);
  const uint32_t suW = (uint32_t)__cvta_generic_to_shared(sWb);

  float acc[8][4];
#pragma unroll
  for (int nt = 0; nt < 8; nt++)
#pragma unroll
    for (int j = 0; j < 4; j++) acc[nt][j] = 0.f;

  {
#pragma unroll
    for (int i = 0; i < 8; i++) {
      int idx = t + 256 * i;
      int r = idx >> 4;
      int c = (idx & 15) << 2;
      cp16(suX + (r * GX_STR + c) * 4, X + (size_t)(m0 + r) * Kd + c);
    }
#pragma unroll
    for (int i = 0; i < 4; i++) {
      int idx = t + 256 * i;
      int r = idx >> 4;
      int c = (idx & 15) << 2;
      cp16(suW + (r * GW_STR + c) * 4, W + (size_t)(n0 + r) * Kd + c);
    }
    asm volatile("cp.async.commit_group;" ::: "memory");
  }

  for (int kc = 0; kc < 8; kc++) {
    const int cur = kc & 1;
    const float* sX = sXb + cur * 128 * GX_STR;
    const float* sW = sWb + cur * 64 * GW_STR;

    __syncthreads();

    if (kc + 1 < 8) {
      const int nxt = cur ^ 1;
      const int koff = (kc + 1) * 64;
      const uint32_t dX = suX + nxt * 128 * GX_STR * 4;
      const uint32_t dW = suW + nxt * 64 * GW_STR * 4;
#pragma unroll
      for (int i = 0; i < 8; i++) {
        int idx = t + 256 * i;
        int r = idx >> 4;
        int c = (idx & 15) << 2;
        cp16(dX + (r * GX_STR + c) * 4, X + (size_t)(m0 + r) * Kd + koff + c);
      }
#pragma unroll
      for (int i = 0; i < 4; i++) {
        int idx = t + 256 * i;
        int r = idx >> 4;
        int c = (idx & 15) << 2;
        cp16(dW + (r * GW_STR + c) * 4, W + (size_t)(n0 + r) * Kd + koff + c);
      }
    }
    asm volatile("cp.async.commit_group;" ::: "memory");
    asm volatile("cp.async.wait_group 1;" ::: "memory");
    __syncthreads();

#pragma unroll
    for (int ks = 0; ks < 8; ks++) {
      const float* ax = sX + (16 * w + r4) * GX_STR + 8 * ks + c4;
      uint32_t a0 = __float_as_uint(ax[0]);
      uint32_t a1 = __float_as_uint(ax[8 * GX_STR]);
      uint32_t a2 = __float_as_uint(ax[4]);
      uint32_t a3 = __float_as_uint(ax[8 * GX_STR + 4]);
#pragma unroll
      for (int nt = 0; nt < 8; nt++) {
        const float* bx = sW + (8 * nt + r4) * GW_STR + 8 * ks + c4;
        uint32_t b0 = __float_as_uint(bx[0]);
        uint32_t b1 = __float_as_uint(bx[4]);
        mma_tf32(acc[nt], a0, a1, a2, a3, b0, b1);
      }
    }
  }

  const int row0 = m0 + 16 * w + r4;
#pragma unroll
  for (int nt = 0; nt < 8; nt++) {
    int col = n0 + 8 * nt + 2 * c4;
    float b0 = bias[col], b1 = bias[col + 1];
    float y00 = acc[nt][0] + b0, y01 = acc[nt][1] + b1;
    float y10 = acc[nt][2] + b0, y11 = acc[nt][3] + b1;
    if (ROUND_OUT) {
      y00 = __uint_as_float(f2tf32(y00));
      y01 = __uint_as_float(f2tf32(y01));
      y10 = __uint_as_float(f2tf32(y10));
      y11 = __uint_as_float(f2tf32(y11));
    }
    *reinterpret_cast<float2*>(Y + (size_t)row0 * Nd + col) =
        make_float2(y00, y01);
    *reinterpret_cast<float2*>(Y + (size_t)(row0 + 8) * Nd + col) =
        make_float2(y10, y11);
  }
}

// ---------------------------------------------------------------------------
// Flash attention v6: 4 warps x 32 q-rows (two m16 tiles per warp) so each
// K/V B-fragment LDS feeds two MMAs -> CTA smem traffic halves. 128 threads.
// K/V pre-rounded tf32, cp.async double-buffered, bias bounce, perm-trick PV.
// ---------------------------------------------------------------------------
#define K_STR 68
#define V_STR 72
#define B_STR 68
#define SK_FLOATS (2 * 64 * K_STR)
#define SV_FLOATS (2 * 64 * V_STR)
#define SB_FLOATS (128 * B_STR)
#define ATTN_SMEM ((SK_FLOATS + SV_FLOATS + SB_FLOATS) * (int)sizeof(float))

__global__ __launch_bounds__(128, 2) void attn_mma_kernel(
    const float* __restrict__ Qg, const float* __restrict__ Kg,
    const float* __restrict__ Vg, const float* __restrict__ bias,
    const int* __restrict__ mask, float* __restrict__ Og) {
  extern __shared__ float sm[];
  float* sK0 = sm;
  float* sV0 = sm + SK_FLOATS;
  float* sB = sm + SK_FLOATS + SV_FLOATS;

  const int q0 = blockIdx.x * 128;
  const int h = blockIdx.y >> 1;
  const int b = blockIdx.y & 1;

  const float* Qb = Qg + (size_t)b * SEQ * EMB + h * DHEAD;
  const float* Kb = Kg + (size_t)b * SEQ * EMB + h * DHEAD;
  const float* Vb = Vg + (size_t)b * SEQ * EMB + h * DHEAD;
  const float* Bb = bias + (size_t)h * SEQ * SEQ;

  const int t = threadIdx.x;
  const int w = t >> 5;           // 0..3
  const int lane = t & 31;
  const int r4 = lane >> 2;
  const int c4 = lane & 3;
  const int permr = ((r4 & 1) << 2) | (r4 >> 1);  // [0,4,1,5,2,6,3,7]

  // ---- stage Q (pre-rounded tf32) and pull both m-tiles' fragments ----
#pragma unroll
  for (int i = 0; i < 16; i++) {
    int idx = t + 128 * i;
    int r = idx >> 4;
    int c = (idx & 15) << 2;
    float4 v = *reinterpret_cast<const float4*>(Qb + (size_t)(q0 + r) * EMB + c);
    float* d = sm + r * 68 + c;
    d[0] = v.x; d[1] = v.y; d[2] = v.z; d[3] = v.w;
  }
  __syncthreads();
  uint32_t qa[2][8][4];
#pragma unroll
  for (int mi = 0; mi < 2; mi++)
#pragma unroll
    for (int ks = 0; ks < 8; ks++) {
      const float* ax = sm + (32 * w + 16 * mi + r4) * 68 + 8 * ks + c4;
      qa[mi][ks][0] = __float_as_uint(ax[0]);
      qa[mi][ks][1] = __float_as_uint(ax[8 * 68]);
      qa[mi][ks][2] = __float_as_uint(ax[4]);
      qa[mi][ks][3] = __float_as_uint(ax[8 * 68 + 4]);
    }
  __syncthreads();

  float* sBw = sB + w * 32 * B_STR;

  float mS[2][2], lS[2][2];
#pragma unroll
  for (int mi = 0; mi < 2; mi++) {
    mS[mi][0] = -1e30f; mS[mi][1] = -1e30f;
    lS[mi][0] = 0.f;    lS[mi][1] = 0.f;
  }
  float acc[2][8][4];
#pragma unroll
  for (int mi = 0; mi < 2; mi++)
#pragma unroll
    for (int nt = 0; nt < 8; nt++)
#pragma unroll
      for (int j = 0; j < 4; j++) acc[mi][nt][j] = 0.f;

  const uint32_t suK = (uint32_t)__cvta_generic_to_shared(sK0);
  const uint32_t suV = (uint32_t)__cvta_generic_to_shared(sV0);

  // prologue: tile 0 -> buf 0 (128 threads: 8 float4 each for K and V)
  {
#pragma unroll
    for (int i = 0; i < 8; i++) {
      int idx = t + 128 * i;
      int r = idx >> 4;
      int c = (idx & 15) << 2;
      cp16(suK + (r * K_STR + c) * 4, Kb + (size_t)r * EMB + c);
      cp16(suV + (r * V_STR + c) * 4, Vb + (size_t)r * EMB + c);
    }
    asm volatile("cp.async.commit_group;" ::: "memory");
  }

  for (int kt = 0; kt < 64; kt++) {
    const int cur = kt & 1;
    const float* sKc = sK0 + cur * 64 * K_STR;
    const float* sVc = sV0 + cur * 64 * V_STR;

    __syncthreads();

    if (kt + 1 < 64) {
      const int nxt = cur ^ 1;
      const float* Ksrc = Kb + (size_t)(kt + 1) * 64 * EMB;
      const float* Vsrc = Vb + (size_t)(kt + 1) * 64 * EMB;
      const uint32_t dK = suK + nxt * 64 * K_STR * 4;
      const uint32_t dV = suV + nxt * 64 * V_STR * 4;
#pragma unroll
      for (int i = 0; i < 8; i++) {
        int idx = t + 128 * i;
        int r = idx >> 4;
        int c = (idx & 15) << 2;
        cp16(dK + (r * K_STR + c) * 4, Ksrc + (size_t)r * EMB + c);
        cp16(dV + (r * V_STR + c) * 4, Vsrc + (size_t)r * EMB + c);
      }
    }
    asm volatile("cp.async.commit_group;" ::: "memory");

    // ---- fused bias+mask bounce: 32 rows per warp ----
    {
      const int k0 = kt * 64;
      const int hl = lane >> 4;
      const int cl = (lane & 15) << 2;
#pragma unroll
      for (int i = 0; i < 16; i++) {
        int rl = 2 * i + hl;
        size_t off = (size_t)(q0 + 32 * w + rl) * SEQ + k0 + cl;
        float4 bv = *reinterpret_cast<const float4*>(Bb + off);
        int4 mv = *reinterpret_cast<const int4*>(mask + off);
        float4 f;
        f.x = mv.x ? bv.x : -1e20f;
        f.y = mv.y ? bv.y : -1e20f;
        f.z = mv.z ? bv.z : -1e20f;
        f.w = mv.w ? bv.w : -1e20f;
        *reinterpret_cast<float4*>(sBw + rl * B_STR + cl) = f;
      }
    }

    asm volatile("cp.async.wait_group 1;" ::: "memory");
    __syncthreads();

    // ---- S = Q @ K^T : each B-fragment pair feeds TWO m-tiles ----
    float S[2][8][4];
#pragma unroll
    for (int mi = 0; mi < 2; mi++)
#pragma unroll
      for (int nt = 0; nt < 8; nt++)
#pragma unroll
        for (int j = 0; j < 4; j++) S[mi][nt][j] = 0.f;

#pragma unroll
    for (int ks = 0; ks < 8; ks++) {
      const float* kb = sKc + permr * K_STR + 8 * ks + c4;
#pragma unroll
      for (int nt = 0; nt < 8; nt++) {
        uint32_t b0 = __float_as_uint(kb[8 * nt * K_STR]);
        uint32_t b1 = __float_as_uint(kb[8 * nt * K_STR + 4]);
        mma_tf32(S[0][nt], qa[0][ks][0], qa[0][ks][1], qa[0][ks][2],
                 qa[0][ks][3], b0, b1);
        mma_tf32(S[1][nt], qa[1][ks][0], qa[1][ks][1], qa[1][ks][2],
                 qa[1][ks][3], b0, b1);
      }
    }

    // ---- softmax per m-tile ----
#pragma unroll
    for (int mi = 0; mi < 2; mi++) {
      const float* bb0 = sBw + (16 * mi + r4) * B_STR;
      const float* bb1 = sBw + (16 * mi + r4 + 8) * B_STR;
      float mx0 = -1e30f, mx1 = -1e30f;
#pragma unroll
      for (int nt = 0; nt < 8; nt++) {
        int cc = 8 * nt + c4;
        float s0 = (S[mi][nt][0] + bb0[cc]) * 0.125f;
        float s1 = (S[mi][nt][1] + bb0[cc + 4]) * 0.125f;
        float s2 = (S[mi][nt][2] + bb1[cc]) * 0.125f;
        float s3 = (S[mi][nt][3] + bb1[cc + 4]) * 0.125f;
        S[mi][nt][0] = s0; S[mi][nt][1] = s1;
        S[mi][nt][2] = s2; S[mi][nt][3] = s3;
        mx0 = fmaxf(mx0, fmaxf(s0, s1));
        mx1 = fmaxf(mx1, fmaxf(s2, s3));
      }
      mx0 = fmaxf(mx0, __shfl_xor_sync(0xffffffffu, mx0, 1));
      mx0 = fmaxf(mx0, __shfl_xor_sync(0xffffffffu, mx0, 2));
      mx1 = fmaxf(mx1, __shfl_xor_sync(0xffffffffu, mx1, 1));
      mx1 = fmaxf(mx1, __shfl_xor_sync(0xffffffffu, mx1, 2));

      float mn0 = fmaxf(mS[mi][0], mx0);
      float mn1 = fmaxf(mS[mi][1], mx1);
      float corr0 = __expf(mS[mi][0] - mn0);
      float corr1 = __expf(mS[mi][1] - mn1);
      mS[mi][0] = mn0; mS[mi][1] = mn1;

      float sum0 = 0.f, sum1 = 0.f;
#pragma unroll
      for (int nt = 0; nt < 8; nt++) {
        float p0 = __expf(S[mi][nt][0] - mn0);
        float p1 = __expf(S[mi][nt][1] - mn0);
        float p2 = __expf(S[mi][nt][2] - mn1);
        float p3 = __expf(S[mi][nt][3] - mn1);
        // store tf32-converted P back into S (bit pattern)
        S[mi][nt][0] = __uint_as_float(f2tf32(p0));
        S[mi][nt][1] = __uint_as_float(f2tf32(p1));
        S[mi][nt][2] = __uint_as_float(f2tf32(p2));
        S[mi][nt][3] = __uint_as_float(f2tf32(p3));
        sum0 += p0 + p1;
        sum1 += p2 + p3;
      }
      sum0 += __shfl_xor_sync(0xffffffffu, sum0, 1);
      sum0 += __shfl_xor_sync(0xffffffffu, sum0, 2);
      sum1 += __shfl_xor_sync(0xffffffffu, sum1, 1);
      sum1 += __shfl_xor_sync(0xffffffffu, sum1, 2);
      lS[mi][0] = lS[mi][0] * corr0 + sum0;
      lS[mi][1] = lS[mi][1] * corr1 + sum1;

#pragma unroll
      for (int nt = 0; nt < 8; nt++) {
        acc[mi][nt][0] *= corr0; acc[mi][nt][1] *= corr0;
        acc[mi][nt][2] *= corr1; acc[mi][nt][3] *= corr1;
      }
    }

    // ---- PV: shared V B-fragments feed both m-tiles ----
#pragma unroll
    for (int t8 = 0; t8 < 8; t8++) {
      const float* vb = sVc + (8 * t8 + c4) * V_STR + r4;
#pragma unroll
      for (int nt = 0; nt < 8; nt++) {
        uint32_t b0 = __float_as_uint(vb[8 * nt]);
        uint32_t b1 = __float_as_uint(vb[4 * V_STR + 8 * nt]);
        mma_tf32(acc[0][nt], __float_as_uint(S[0][t8][0]),
                 __float_as_uint(S[0][t8][2]), __float_as_uint(S[0][t8][1]),
                 __float_as_uint(S[0][t8][3]), b0, b1);
        mma_tf32(acc[1][nt], __float_as_uint(S[1][t8][0]),
                 __float_as_uint(S[1][t8][2]), __float_as_uint(S[1][t8][1]),
                 __float_as_uint(S[1][t8][3]), b0, b1);
      }
    }
  }

  // ---- epilogue: round O to tf32 ----
#pragma unroll
  for (int mi = 0; mi < 2; mi++) {
    float inv0 = 1.0f / lS[mi][0];
    float inv1 = 1.0f / lS[mi][1];
    int qr0 = q0 + 32 * w + 16 * mi + r4;
    float* o0 = Og + (size_t)(b * SEQ + qr0) * EMB + h * DHEAD;
    float* o1 = Og + (size_t)(b * SEQ + qr0 + 8) * EMB + h * DHEAD;
#pragma unroll
    for (int nt = 0; nt < 8; nt++) {
      int col = 8 * nt + 2 * c4;
      *reinterpret_cast<float2*>(o0 + col) =
          make_float2(__uint_as_float(f2tf32(acc[mi][nt][0] * inv0)),
                      __uint_as_float(f2tf32(acc[mi][nt][1] * inv0)));
      *reinterpret_cast<float2*>(o1 + col) =
          make_float2(__uint_as_float(f2tf32(acc[mi][nt][2] * inv1)),
                      __uint_as_float(f2tf32(acc[mi][nt][3] * inv1)));
    }
  }
}

// ---------------------------------------------------------------------------
extern "C" void kernel_launch(void* const* d_in, const int* in_sizes, int n_in,
                              void* d_out, int out_size) {
  const float* x    = (const float*)d_in[0];
  const float* bias = (const float*)d_in[1];
  const int*   mask = (const int*)d_in[2];
  const float* Wq   = (const float*)d_in[3];
  const float* bq   = (const float*)d_in[4];
  const float* Wk   = (const float*)d_in[5];
  const float* bk   = (const float*)d_in[6];
  const float* Wv   = (const float*)d_in[7];
  const float* bv   = (const float*)d_in[8];
  const float* Wo   = (const float*)d_in[9];
  const float* bo   = (const float*)d_in[10];
  float* out = (float*)d_out;

  float *pq, *pk, *pv, *po, *px, *pwq, *pwk, *pwv, *pwo;
  cudaGetSymbolAddress((void**)&pq, g_q);
  cudaGetSymbolAddress((void**)&pk, g_k);
  cudaGetSymbolAddress((void**)&pv, g_v);
  cudaGetSymbolAddress((void**)&po, g_o);
  cudaGetSymbolAddress((void**)&px, g_x);
  cudaGetSymbolAddress((void**)&pwq, g_wq);
  cudaGetSymbolAddress((void**)&pwk, g_wk);
  cudaGetSymbolAddress((void**)&pwv, g_wv);
  cudaGetSymbolAddress((void**)&pwo, g_wo);

  cudaFuncSetAttribute(gemm_mma_kernel<true>,
                       cudaFuncAttributeMaxDynamicSharedMemorySize, GEMM_SMEM);
  cudaFuncSetAttribute(gemm_mma_kernel<false>,
                       cudaFuncAttributeMaxDynamicSharedMemorySize, GEMM_SMEM);
  cudaFuncSetAttribute(attn_mma_kernel,
                       cudaFuncAttributeMaxDynamicSharedMemorySize, ATTN_SMEM);

  const int nx4 = BATCH * SEQ * EMB / 4;
  const int nw4 = EMB * EMB / 4;
  round_tf32_kernel<<<(nx4 + 255) / 256, 256>>>(x, px, nx4);
  round_tf32_kernel<<<(nw4 + 255) / 256, 256>>>(Wq, pwq, nw4);
  round_tf32_kernel<<<(nw4 + 255) / 256, 256>>>(Wk, pwk, nw4);
  round_tf32_kernel<<<(nw4 + 255) / 256, 256>>>(Wv, pwv, nw4);
  round_tf32_kernel<<<(nw4 + 255) / 256, 256>>>(Wo, pwo, nw4);

  dim3 gg(BATCH * SEQ / 128, EMB / 64);  // (64, 8)
  gemm_mma_kernel<true><<<gg, 256, GEMM_SMEM>>>(px, pwq, bq, pq);
  gemm_mma_kernel<true><<<gg, 256, GEMM_SMEM>>>(px, pwk, bk, pk);
  gemm_mma_kernel<true><<<gg, 256, GEMM_SMEM>>>(px, pwv, bv, pv);

  dim3 ga(SEQ / 128, HEADS * BATCH);  // (32, 16)
  attn_mma_kernel<<<ga, 128, ATTN_SMEM>>>(pq, pk, pv, bias, mask, po);

  gemm_mma_kernel<false><<<gg, 256, GEMM_SMEM>>>(po, pwo, bo, out);
}